// round 7
// baseline (speedup 1.0000x reference)
#include <cuda_runtime.h>

typedef unsigned long long ull;

#define BATCH 8
#define CH    64
#define MID   8
#define NPIX  4096
#define TQ    128
#define TJ    64

// Scratch (no allocations allowed -> __device__ globals)
__device__ float g_q[BATCH * NPIX * MID];   // [b][i][m]
__device__ float g_k[BATCH * NPIX * MID];   // [b][j][m]
__device__ float g_v[BATCH * NPIX * CH];    // [b][j][c]

// ---------------------------------------------------------------------------
// Projection kernel: q = Wq x + bq, k = Wk x + bk, v = Wv x + bv  (1x1 convs)
// One thread per pixel. Weights transposed in SMEM for broadcast float4 reads.
// ---------------------------------------------------------------------------
__global__ __launch_bounds__(256) void proj_kernel(
    const float* __restrict__ x,
    const float* __restrict__ wq, const float* __restrict__ bq,
    const float* __restrict__ wk, const float* __restrict__ bk,
    const float* __restrict__ wv, const float* __restrict__ bv)
{
    __shared__ float s_wvT[CH * CH];     // [c][d]
    __shared__ float s_wqT[CH * MID];    // [c][m]
    __shared__ float s_wkT[CH * MID];    // [c][m]
    __shared__ float s_bq[MID], s_bk[MID], s_bv[CH];

    const int tid = threadIdx.x;
    for (int idx = tid; idx < CH * CH; idx += 256) {
        int d = idx >> 6, c = idx & 63;
        s_wvT[c * CH + d] = wv[idx];
    }
    for (int idx = tid; idx < MID * CH; idx += 256) {
        int m = idx >> 6, c = idx & 63;
        s_wqT[c * MID + m] = wq[idx];
        s_wkT[c * MID + m] = wk[idx];
    }
    if (tid < MID) { s_bq[tid] = bq[tid]; s_bk[tid] = bk[tid]; }
    if (tid < CH)  { s_bv[tid] = bv[tid]; }
    __syncthreads();

    const int g = blockIdx.x * 256 + tid;    // global pixel id = b*NPIX + n
    const int b = g >> 12;
    const int n = g & (NPIX - 1);

    float q[MID], k[MID], v[CH];
    #pragma unroll
    for (int m = 0; m < MID; m++) { q[m] = s_bq[m]; k[m] = s_bk[m]; }
    #pragma unroll
    for (int d = 0; d < CH; d++) v[d] = s_bv[d];

    const float* xp = x + (size_t)b * CH * NPIX + n;
    for (int c = 0; c < CH; c++) {
        float xv = xp[(size_t)c * NPIX];
        #pragma unroll
        for (int m = 0; m < MID; m++) {
            q[m] = fmaf(s_wqT[c * MID + m], xv, q[m]);
            k[m] = fmaf(s_wkT[c * MID + m], xv, k[m]);
        }
        #pragma unroll
        for (int d = 0; d < CH; d++)
            v[d] = fmaf(s_wvT[c * CH + d], xv, v[d]);
    }

    float4* qo = (float4*)&g_q[(size_t)g * MID];
    qo[0] = make_float4(q[0], q[1], q[2], q[3]);
    qo[1] = make_float4(q[4], q[5], q[6], q[7]);
    float4* ko = (float4*)&g_k[(size_t)g * MID];
    ko[0] = make_float4(k[0], k[1], k[2], k[3]);
    ko[1] = make_float4(k[4], k[5], k[6], k[7]);
    float4* vo = (float4*)&g_v[(size_t)g * CH];
    #pragma unroll
    for (int r = 0; r < 16; r++)
        vo[r] = make_float4(v[4 * r], v[4 * r + 1], v[4 * r + 2], v[4 * r + 3]);
}

// ---------------------------------------------------------------------------
// Attention kernel. One block = (batch b, 128-query tile).
// Unnormalized softmax (safe for these magnitudes in fp32):
//   num[i][c] = sum_j exp(q_i . k_j) * v[c][j],  Z_i = sum_j exp(q_i . k_j)
//   out = x + gamma * num / Z
// PV accumulation uses packed fma.rn.f32x2 (2x fp32 FMA rate on sm_103a).
// ---------------------------------------------------------------------------
#define FMA_X2(acc, a, bb) \
    asm("fma.rn.f32x2 %0, %1, %2, %0;" : "+l"(acc) : "l"(a), "l"(bb))

// dyn SMEM layout (floats):
//  q_s : [0,      1024)   TQ*8
//  k_s : [1024,   1536)   TJ*8
//  z_s : [1536,   1792)   TQ*2 partial Z
//  e_s : [1792,   9984)   TJ*TQ exp tile  (reused as out staging)
//  v_s : [9984,  18176)   TJ*CH float2 {v,v}
#define SMEM_FLOATS 18176
#define SMEM_BYTES  (SMEM_FLOATS * 4)

__global__ __launch_bounds__(256) void attn_kernel(
    const float* __restrict__ x,
    const float* __restrict__ gamma,
    float* __restrict__ out)
{
    extern __shared__ float smem[];
    float*  q_s = smem;
    float*  k_s = smem + 1024;
    float*  z_s = smem + 1536;
    float*  e_s = smem + 1792;
    float2* v_s = (float2*)(smem + 9984);

    const int tid = threadIdx.x;
    const int b   = blockIdx.y;
    const int i0g = blockIdx.x * TQ;

    // load 128 queries (1024 floats) + zero Z partials
    ((float4*)q_s)[tid] =
        ((const float4*)(g_q + ((size_t)b * NPIX + i0g) * MID))[tid];
    z_s[tid] = 0.0f;
    __syncthreads();

    // E-phase mapping: 1 query per thread, half the j-tile each
    const int il = tid & 127;
    const int jh = tid >> 7;
    const float4 qa = ((const float4*)q_s)[il * 2];
    const float4 qb = ((const float4*)q_s)[il * 2 + 1];

    // GEMM mapping: 8 i-rows (4 pairs) x 4 channels per thread
    const int ti = tid & 15, tc = tid >> 4;
    const int i0 = ti * 8,   c0 = tc * 4;

    ull acc[4][4];
    #pragma unroll
    for (int p = 0; p < 4; p++)
        #pragma unroll
        for (int cc = 0; cc < 4; cc++) acc[p][cc] = 0ull;

    const float* kg_base = g_k + (size_t)b * NPIX * MID;
    const float* vg_base = g_v + (size_t)b * NPIX * CH;

    for (int jt = 0; jt < NPIX / TJ; jt++) {
        const int j0 = jt * TJ;
        __syncthreads();  // previous GEMM done reading e_s/v_s

        if (tid < 128)
            ((float4*)k_s)[tid] = ((const float4*)(kg_base + (size_t)j0 * MID))[tid];
        const float* vg = vg_base + (size_t)j0 * CH;
        #pragma unroll
        for (int r = 0; r < 16; r++) {
            int idx = r * 256 + tid;
            float vv = vg[idx];
            v_s[idx] = make_float2(vv, vv);
        }
        __syncthreads();

        // ---- E phase: e = exp(q.k), accumulate partial Z ----
        float zloc = 0.0f;
        #pragma unroll 4
        for (int jj = 0; jj < 32; jj++) {
            int j = jh * 32 + jj;
            float4 ka = ((const float4*)k_s)[j * 2];
            float4 kb = ((const float4*)k_s)[j * 2 + 1];
            float s = qa.x * ka.x + qa.y * ka.y + qa.z * ka.z + qa.w * ka.w
                    + qb.x * kb.x + qb.y * kb.y + qb.z * kb.z + qb.w * kb.w;
            float e = __expf(s);
            zloc += e;
            e_s[j * 128 + il] = e;
        }
        z_s[il * 2 + jh] += zloc;   // unique owner per (il, jh)
        __syncthreads();

        // ---- GEMM phase: acc += E_pair * {v,v}  (packed f32x2) ----
        #pragma unroll 2
        for (int j = 0; j < TJ; j++) {
            ulonglong2 eA = *(const ulonglong2*)&e_s[j * 128 + i0];
            ulonglong2 eB = *(const ulonglong2*)&e_s[j * 128 + i0 + 4];
            ull vp0 = *(const ull*)&v_s[j * 64 + c0 + 0];
            ull vp1 = *(const ull*)&v_s[j * 64 + c0 + 1];
            ull vp2 = *(const ull*)&v_s[j * 64 + c0 + 2];
            ull vp3 = *(const ull*)&v_s[j * 64 + c0 + 3];
            FMA_X2(acc[0][0], eA.x, vp0); FMA_X2(acc[0][1], eA.x, vp1);
            FMA_X2(acc[0][2], eA.x, vp2); FMA_X2(acc[0][3], eA.x, vp3);
            FMA_X2(acc[1][0], eA.y, vp0); FMA_X2(acc[1][1], eA.y, vp1);
            FMA_X2(acc[1][2], eA.y, vp2); FMA_X2(acc[1][3], eA.y, vp3);
            FMA_X2(acc[2][0], eB.x, vp0); FMA_X2(acc[2][1], eB.x, vp1);
            FMA_X2(acc[2][2], eB.x, vp2); FMA_X2(acc[2][3], eB.x, vp3);
            FMA_X2(acc[3][0], eB.y, vp0); FMA_X2(acc[3][1], eB.y, vp1);
            FMA_X2(acc[3][2], eB.y, vp2); FMA_X2(acc[3][3], eB.y, vp3);
        }
    }
    __syncthreads();   // all GEMM reads of e_s done -> reuse as out staging

    // stage num[i][c] into out_s[c][i] for coalesced writes
    float* out_s = e_s;  // 64*128 floats
    #pragma unroll
    for (int p = 0; p < 4; p++)
        #pragma unroll
        for (int cc = 0; cc < 4; cc++) {
            float2 f = *(float2*)&acc[p][cc];
            *(float2*)&out_s[(c0 + cc) * 128 + i0 + 2 * p] = f;
        }
    // reciprocal Z into (now-dead) q_s
    if (tid < 128) q_s[tid] = 1.0f / (z_s[tid * 2] + z_s[tid * 2 + 1]);
    __syncthreads();

    const float gm = gamma[0];
    #pragma unroll
    for (int r = 0; r < 32; r++) {
        int e  = r * 256 + tid;
        int c  = e >> 7;
        int ii = e & 127;
        size_t gi = ((size_t)(b * CH + c)) * NPIX + i0g + ii;
        out[gi] = x[gi] + gm * out_s[e] * q_s[ii];
    }
}

// ---------------------------------------------------------------------------
extern "C" void kernel_launch(void* const* d_in, const int* in_sizes, int n_in,
                              void* d_out, int out_size)
{
    const float* x     = (const float*)d_in[0];
    const float* wq    = (const float*)d_in[1];
    const float* bq    = (const float*)d_in[2];
    const float* wk    = (const float*)d_in[3];
    const float* bk    = (const float*)d_in[4];
    const float* wv    = (const float*)d_in[5];
    const float* bv    = (const float*)d_in[6];
    const float* gamma = (const float*)d_in[7];
    float* out = (float*)d_out;

    cudaFuncSetAttribute(attn_kernel,
                         cudaFuncAttributeMaxDynamicSharedMemorySize,
                         SMEM_BYTES);

    proj_kernel<<<(BATCH * NPIX) / 256, 256>>>(x, wq, bq, wk, bk, wv, bv);
    attn_kernel<<<dim3(NPIX / TQ, BATCH), 256, SMEM_BYTES>>>(x, gamma, out);
}

// round 8
// speedup vs baseline: 1.0017x; 1.0017x over previous
#include <cuda_runtime.h>

typedef unsigned long long ull;

#define BATCH 8
#define CH    64
#define MID   8
#define NPIX  4096
#define TQ    128
#define TJ    64

// Scratch (no allocations allowed -> __device__ globals)
__device__ float g_q[BATCH * NPIX * MID];   // [b][i][m]
__device__ float g_k[BATCH * NPIX * MID];   // [b][j][m]
__device__ float g_v[BATCH * NPIX * CH];    // [b][j][c]

// ---------------------------------------------------------------------------
// Projection kernel: q = Wq x + bq, k = Wk x + bk, v = Wv x + bv  (1x1 convs)
// One thread per pixel. Weights transposed in SMEM for broadcast float4 reads.
// ---------------------------------------------------------------------------
__global__ __launch_bounds__(256) void proj_kernel(
    const float* __restrict__ x,
    const float* __restrict__ wq, const float* __restrict__ bq,
    const float* __restrict__ wk, const float* __restrict__ bk,
    const float* __restrict__ wv, const float* __restrict__ bv)
{
    __shared__ float s_wvT[CH * CH];     // [c][d]
    __shared__ float s_wqT[CH * MID];    // [c][m]
    __shared__ float s_wkT[CH * MID];    // [c][m]
    __shared__ float s_bq[MID], s_bk[MID], s_bv[CH];

    const int tid = threadIdx.x;
    for (int idx = tid; idx < CH * CH; idx += 256) {
        int d = idx >> 6, c = idx & 63;
        s_wvT[c * CH + d] = wv[idx];
    }
    for (int idx = tid; idx < MID * CH; idx += 256) {
        int m = idx >> 6, c = idx & 63;
        s_wqT[c * MID + m] = wq[idx];
        s_wkT[c * MID + m] = wk[idx];
    }
    if (tid < MID) { s_bq[tid] = bq[tid]; s_bk[tid] = bk[tid]; }
    if (tid < CH)  { s_bv[tid] = bv[tid]; }
    __syncthreads();

    const int g = blockIdx.x * 256 + tid;    // global pixel id = b*NPIX + n
    const int b = g >> 12;
    const int n = g & (NPIX - 1);

    float q[MID], k[MID], v[CH];
    #pragma unroll
    for (int m = 0; m < MID; m++) { q[m] = s_bq[m]; k[m] = s_bk[m]; }
    #pragma unroll
    for (int d = 0; d < CH; d++) v[d] = s_bv[d];

    const float* xp = x + (size_t)b * CH * NPIX + n;
    for (int c = 0; c < CH; c++) {
        float xv = xp[(size_t)c * NPIX];
        #pragma unroll
        for (int m = 0; m < MID; m++) {
            q[m] = fmaf(s_wqT[c * MID + m], xv, q[m]);
            k[m] = fmaf(s_wkT[c * MID + m], xv, k[m]);
        }
        #pragma unroll
        for (int d = 0; d < CH; d++)
            v[d] = fmaf(s_wvT[c * CH + d], xv, v[d]);
    }

    float4* qo = (float4*)&g_q[(size_t)g * MID];
    qo[0] = make_float4(q[0], q[1], q[2], q[3]);
    qo[1] = make_float4(q[4], q[5], q[6], q[7]);
    float4* ko = (float4*)&g_k[(size_t)g * MID];
    ko[0] = make_float4(k[0], k[1], k[2], k[3]);
    ko[1] = make_float4(k[4], k[5], k[6], k[7]);
    float4* vo = (float4*)&g_v[(size_t)g * CH];
    #pragma unroll
    for (int r = 0; r < 16; r++)
        vo[r] = make_float4(v[4 * r], v[4 * r + 1], v[4 * r + 2], v[4 * r + 3]);
}

// ---------------------------------------------------------------------------
// Attention kernel. One block = (batch b, 128-query tile).
// Unnormalized softmax (safe for these magnitudes in fp32):
//   num[i][c] = sum_j exp(q_i . k_j) * v[c][j],  Z_i = sum_j exp(q_i . k_j)
//   out = x + gamma * num / Z
// PV accumulation uses packed fma.rn.f32x2 (2x fp32 FMA rate on sm_103a).
// ---------------------------------------------------------------------------
#define FMA_X2(acc, a, bb) \
    asm("fma.rn.f32x2 %0, %1, %2, %0;" : "+l"(acc) : "l"(a), "l"(bb))

// dyn SMEM layout (floats):
//  q_s : [0,      1024)   TQ*8
//  k_s : [1024,   1536)   TJ*8
//  z_s : [1536,   1792)   TQ*2 partial Z
//  e_s : [1792,   9984)   TJ*TQ exp tile  (reused as out staging)
//  v_s : [9984,  18176)   TJ*CH float2 {v,v}
#define SMEM_FLOATS 18176
#define SMEM_BYTES  (SMEM_FLOATS * 4)

__global__ __launch_bounds__(256) void attn_kernel(
    const float* __restrict__ x,
    const float* __restrict__ gamma,
    float* __restrict__ out)
{
    extern __shared__ float smem[];
    float*  q_s = smem;
    float*  k_s = smem + 1024;
    float*  z_s = smem + 1536;
    float*  e_s = smem + 1792;
    float2* v_s = (float2*)(smem + 9984);

    const int tid = threadIdx.x;
    const int b   = blockIdx.y;
    const int i0g = blockIdx.x * TQ;

    // load 128 queries (1024 floats) + zero Z partials
    ((float4*)q_s)[tid] =
        ((const float4*)(g_q + ((size_t)b * NPIX + i0g) * MID))[tid];
    z_s[tid] = 0.0f;
    __syncthreads();

    // E-phase mapping: 1 query per thread, half the j-tile each
    const int il = tid & 127;
    const int jh = tid >> 7;
    const float4 qa = ((const float4*)q_s)[il * 2];
    const float4 qb = ((const float4*)q_s)[il * 2 + 1];

    // GEMM mapping: 8 i-rows (4 pairs) x 4 channels per thread
    const int ti = tid & 15, tc = tid >> 4;
    const int i0 = ti * 8,   c0 = tc * 4;

    ull acc[4][4];
    #pragma unroll
    for (int p = 0; p < 4; p++)
        #pragma unroll
        for (int cc = 0; cc < 4; cc++) acc[p][cc] = 0ull;

    const float* kg_base = g_k + (size_t)b * NPIX * MID;
    const float* vg_base = g_v + (size_t)b * NPIX * CH;

    for (int jt = 0; jt < NPIX / TJ; jt++) {
        const int j0 = jt * TJ;
        __syncthreads();  // previous GEMM done reading e_s/v_s

        if (tid < 128)
            ((float4*)k_s)[tid] = ((const float4*)(kg_base + (size_t)j0 * MID))[tid];
        const float* vg = vg_base + (size_t)j0 * CH;
        #pragma unroll
        for (int r = 0; r < 16; r++) {
            int idx = r * 256 + tid;
            float vv = vg[idx];
            v_s[idx] = make_float2(vv, vv);
        }
        __syncthreads();

        // ---- E phase: e = exp(q.k), accumulate partial Z ----
        float zloc = 0.0f;
        #pragma unroll 4
        for (int jj = 0; jj < 32; jj++) {
            int j = jh * 32 + jj;
            float4 ka = ((const float4*)k_s)[j * 2];
            float4 kb = ((const float4*)k_s)[j * 2 + 1];
            float s = qa.x * ka.x + qa.y * ka.y + qa.z * ka.z + qa.w * ka.w
                    + qb.x * kb.x + qb.y * kb.y + qb.z * kb.z + qb.w * kb.w;
            float e = __expf(s);
            zloc += e;
            e_s[j * 128 + il] = e;
        }
        z_s[il * 2 + jh] += zloc;   // unique owner per (il, jh)
        __syncthreads();

        // ---- GEMM phase: acc += E_pair * {v,v}  (packed f32x2) ----
        #pragma unroll 2
        for (int j = 0; j < TJ; j++) {
            ulonglong2 eA = *(const ulonglong2*)&e_s[j * 128 + i0];
            ulonglong2 eB = *(const ulonglong2*)&e_s[j * 128 + i0 + 4];
            ull vp0 = *(const ull*)&v_s[j * 64 + c0 + 0];
            ull vp1 = *(const ull*)&v_s[j * 64 + c0 + 1];
            ull vp2 = *(const ull*)&v_s[j * 64 + c0 + 2];
            ull vp3 = *(const ull*)&v_s[j * 64 + c0 + 3];
            FMA_X2(acc[0][0], eA.x, vp0); FMA_X2(acc[0][1], eA.x, vp1);
            FMA_X2(acc[0][2], eA.x, vp2); FMA_X2(acc[0][3], eA.x, vp3);
            FMA_X2(acc[1][0], eA.y, vp0); FMA_X2(acc[1][1], eA.y, vp1);
            FMA_X2(acc[1][2], eA.y, vp2); FMA_X2(acc[1][3], eA.y, vp3);
            FMA_X2(acc[2][0], eB.x, vp0); FMA_X2(acc[2][1], eB.x, vp1);
            FMA_X2(acc[2][2], eB.x, vp2); FMA_X2(acc[2][3], eB.x, vp3);
            FMA_X2(acc[3][0], eB.y, vp0); FMA_X2(acc[3][1], eB.y, vp1);
            FMA_X2(acc[3][2], eB.y, vp2); FMA_X2(acc[3][3], eB.y, vp3);
        }
    }
    __syncthreads();   // all GEMM reads of e_s done -> reuse as out staging

    // stage num[i][c] into out_s[c][i] for coalesced writes
    float* out_s = e_s;  // 64*128 floats
    #pragma unroll
    for (int p = 0; p < 4; p++)
        #pragma unroll
        for (int cc = 0; cc < 4; cc++) {
            float2 f = *(float2*)&acc[p][cc];
            *(float2*)&out_s[(c0 + cc) * 128 + i0 + 2 * p] = f;
        }
    // reciprocal Z into (now-dead) q_s
    if (tid < 128) q_s[tid] = 1.0f / (z_s[tid * 2] + z_s[tid * 2 + 1]);
    __syncthreads();

    const float gm = gamma[0];
    #pragma unroll
    for (int r = 0; r < 32; r++) {
        int e  = r * 256 + tid;
        int c  = e >> 7;
        int ii = e & 127;
        size_t gi = ((size_t)(b * CH + c)) * NPIX + i0g + ii;
        out[gi] = x[gi] + gm * out_s[e] * q_s[ii];
    }
}

// ---------------------------------------------------------------------------
extern "C" void kernel_launch(void* const* d_in, const int* in_sizes, int n_in,
                              void* d_out, int out_size)
{
    const float* x     = (const float*)d_in[0];
    const float* wq    = (const float*)d_in[1];
    const float* bq    = (const float*)d_in[2];
    const float* wk    = (const float*)d_in[3];
    const float* bk    = (const float*)d_in[4];
    const float* wv    = (const float*)d_in[5];
    const float* bv    = (const float*)d_in[6];
    const float* gamma = (const float*)d_in[7];
    float* out = (float*)d_out;

    cudaFuncSetAttribute(attn_kernel,
                         cudaFuncAttributeMaxDynamicSharedMemorySize,
                         SMEM_BYTES);

    proj_kernel<<<(BATCH * NPIX) / 256, 256>>>(x, wq, bq, wk, bk, wv, bv);
    attn_kernel<<<dim3(NPIX / TQ, BATCH), 256, SMEM_BYTES>>>(x, gamma, out);
}

// round 9
// speedup vs baseline: 1.0021x; 1.0004x over previous
#include <cuda_runtime.h>

typedef unsigned long long ull;

#define BATCH 8
#define CH    64
#define MID   8
#define NPIX  4096
#define TQ    128
#define TJ    64

// Scratch (no allocations allowed -> __device__ globals)
__device__ float g_q[BATCH * NPIX * MID];   // [b][i][m]
__device__ float g_k[BATCH * NPIX * MID];   // [b][j][m]
__device__ float g_v[BATCH * NPIX * CH];    // [b][j][c]

// ---------------------------------------------------------------------------
// Projection kernel: q = Wq x + bq, k = Wk x + bk, v = Wv x + bv  (1x1 convs)
// One thread per pixel. Weights transposed in SMEM for broadcast float4 reads.
// ---------------------------------------------------------------------------
__global__ __launch_bounds__(256) void proj_kernel(
    const float* __restrict__ x,
    const float* __restrict__ wq, const float* __restrict__ bq,
    const float* __restrict__ wk, const float* __restrict__ bk,
    const float* __restrict__ wv, const float* __restrict__ bv)
{
    __shared__ float s_wvT[CH * CH];     // [c][d]
    __shared__ float s_wqT[CH * MID];    // [c][m]
    __shared__ float s_wkT[CH * MID];    // [c][m]
    __shared__ float s_bq[MID], s_bk[MID], s_bv[CH];

    const int tid = threadIdx.x;
    for (int idx = tid; idx < CH * CH; idx += 256) {
        int d = idx >> 6, c = idx & 63;
        s_wvT[c * CH + d] = wv[idx];
    }
    for (int idx = tid; idx < MID * CH; idx += 256) {
        int m = idx >> 6, c = idx & 63;
        s_wqT[c * MID + m] = wq[idx];
        s_wkT[c * MID + m] = wk[idx];
    }
    if (tid < MID) { s_bq[tid] = bq[tid]; s_bk[tid] = bk[tid]; }
    if (tid < CH)  { s_bv[tid] = bv[tid]; }
    __syncthreads();

    const int g = blockIdx.x * 256 + tid;    // global pixel id = b*NPIX + n
    const int b = g >> 12;
    const int n = g & (NPIX - 1);

    float q[MID], k[MID], v[CH];
    #pragma unroll
    for (int m = 0; m < MID; m++) { q[m] = s_bq[m]; k[m] = s_bk[m]; }
    #pragma unroll
    for (int d = 0; d < CH; d++) v[d] = s_bv[d];

    const float* xp = x + (size_t)b * CH * NPIX + n;
    for (int c = 0; c < CH; c++) {
        float xv = xp[(size_t)c * NPIX];
        #pragma unroll
        for (int m = 0; m < MID; m++) {
            q[m] = fmaf(s_wqT[c * MID + m], xv, q[m]);
            k[m] = fmaf(s_wkT[c * MID + m], xv, k[m]);
        }
        #pragma unroll
        for (int d = 0; d < CH; d++)
            v[d] = fmaf(s_wvT[c * CH + d], xv, v[d]);
    }

    float4* qo = (float4*)&g_q[(size_t)g * MID];
    qo[0] = make_float4(q[0], q[1], q[2], q[3]);
    qo[1] = make_float4(q[4], q[5], q[6], q[7]);
    float4* ko = (float4*)&g_k[(size_t)g * MID];
    ko[0] = make_float4(k[0], k[1], k[2], k[3]);
    ko[1] = make_float4(k[4], k[5], k[6], k[7]);
    float4* vo = (float4*)&g_v[(size_t)g * CH];
    #pragma unroll
    for (int r = 0; r < 16; r++)
        vo[r] = make_float4(v[4 * r], v[4 * r + 1], v[4 * r + 2], v[4 * r + 3]);
}

// ---------------------------------------------------------------------------
// Attention kernel. One block = (batch b, 128-query tile).
// Unnormalized softmax (safe for these magnitudes in fp32):
//   num[i][c] = sum_j exp(q_i . k_j) * v[c][j],  Z_i = sum_j exp(q_i . k_j)
//   out = x + gamma * num / Z
// PV accumulation uses packed fma.rn.f32x2 (2x fp32 FMA rate on sm_103a).
// ---------------------------------------------------------------------------
#define FMA_X2(acc, a, bb) \
    asm("fma.rn.f32x2 %0, %1, %2, %0;" : "+l"(acc) : "l"(a), "l"(bb))

// dyn SMEM layout (floats):
//  q_s : [0,      1024)   TQ*8
//  k_s : [1024,   1536)   TJ*8
//  z_s : [1536,   1792)   TQ*2 partial Z
//  e_s : [1792,   9984)   TJ*TQ exp tile  (reused as out staging)
//  v_s : [9984,  18176)   TJ*CH float2 {v,v}
#define SMEM_FLOATS 18176
#define SMEM_BYTES  (SMEM_FLOATS * 4)

__global__ __launch_bounds__(256) void attn_kernel(
    const float* __restrict__ x,
    const float* __restrict__ gamma,
    float* __restrict__ out)
{
    extern __shared__ float smem[];
    float*  q_s = smem;
    float*  k_s = smem + 1024;
    float*  z_s = smem + 1536;
    float*  e_s = smem + 1792;
    float2* v_s = (float2*)(smem + 9984);

    const int tid = threadIdx.x;
    const int b   = blockIdx.y;
    const int i0g = blockIdx.x * TQ;

    // load 128 queries (1024 floats) + zero Z partials
    ((float4*)q_s)[tid] =
        ((const float4*)(g_q + ((size_t)b * NPIX + i0g) * MID))[tid];
    z_s[tid] = 0.0f;
    __syncthreads();

    // E-phase mapping: 1 query per thread, half the j-tile each
    const int il = tid & 127;
    const int jh = tid >> 7;
    const float4 qa = ((const float4*)q_s)[il * 2];
    const float4 qb = ((const float4*)q_s)[il * 2 + 1];

    // GEMM mapping: 8 i-rows (4 pairs) x 4 channels per thread
    const int ti = tid & 15, tc = tid >> 4;
    const int i0 = ti * 8,   c0 = tc * 4;

    ull acc[4][4];
    #pragma unroll
    for (int p = 0; p < 4; p++)
        #pragma unroll
        for (int cc = 0; cc < 4; cc++) acc[p][cc] = 0ull;

    const float* kg_base = g_k + (size_t)b * NPIX * MID;
    const float* vg_base = g_v + (size_t)b * NPIX * CH;

    for (int jt = 0; jt < NPIX / TJ; jt++) {
        const int j0 = jt * TJ;
        __syncthreads();  // previous GEMM done reading e_s/v_s

        if (tid < 128)
            ((float4*)k_s)[tid] = ((const float4*)(kg_base + (size_t)j0 * MID))[tid];
        const float* vg = vg_base + (size_t)j0 * CH;
        #pragma unroll
        for (int r = 0; r < 16; r++) {
            int idx = r * 256 + tid;
            float vv = vg[idx];
            v_s[idx] = make_float2(vv, vv);
        }
        __syncthreads();

        // ---- E phase: e = exp(q.k), accumulate partial Z ----
        float zloc = 0.0f;
        #pragma unroll 4
        for (int jj = 0; jj < 32; jj++) {
            int j = jh * 32 + jj;
            float4 ka = ((const float4*)k_s)[j * 2];
            float4 kb = ((const float4*)k_s)[j * 2 + 1];
            float s = qa.x * ka.x + qa.y * ka.y + qa.z * ka.z + qa.w * ka.w
                    + qb.x * kb.x + qb.y * kb.y + qb.z * kb.z + qb.w * kb.w;
            float e = __expf(s);
            zloc += e;
            e_s[j * 128 + il] = e;
        }
        z_s[il * 2 + jh] += zloc;   // unique owner per (il, jh)
        __syncthreads();

        // ---- GEMM phase: acc += E_pair * {v,v}  (packed f32x2) ----
        #pragma unroll 2
        for (int j = 0; j < TJ; j++) {
            ulonglong2 eA = *(const ulonglong2*)&e_s[j * 128 + i0];
            ulonglong2 eB = *(const ulonglong2*)&e_s[j * 128 + i0 + 4];
            ull vp0 = *(const ull*)&v_s[j * 64 + c0 + 0];
            ull vp1 = *(const ull*)&v_s[j * 64 + c0 + 1];
            ull vp2 = *(const ull*)&v_s[j * 64 + c0 + 2];
            ull vp3 = *(const ull*)&v_s[j * 64 + c0 + 3];
            FMA_X2(acc[0][0], eA.x, vp0); FMA_X2(acc[0][1], eA.x, vp1);
            FMA_X2(acc[0][2], eA.x, vp2); FMA_X2(acc[0][3], eA.x, vp3);
            FMA_X2(acc[1][0], eA.y, vp0); FMA_X2(acc[1][1], eA.y, vp1);
            FMA_X2(acc[1][2], eA.y, vp2); FMA_X2(acc[1][3], eA.y, vp3);
            FMA_X2(acc[2][0], eB.x, vp0); FMA_X2(acc[2][1], eB.x, vp1);
            FMA_X2(acc[2][2], eB.x, vp2); FMA_X2(acc[2][3], eB.x, vp3);
            FMA_X2(acc[3][0], eB.y, vp0); FMA_X2(acc[3][1], eB.y, vp1);
            FMA_X2(acc[3][2], eB.y, vp2); FMA_X2(acc[3][3], eB.y, vp3);
        }
    }
    __syncthreads();   // all GEMM reads of e_s done -> reuse as out staging

    // stage num[i][c] into out_s[c][i] for coalesced writes
    float* out_s = e_s;  // 64*128 floats
    #pragma unroll
    for (int p = 0; p < 4; p++)
        #pragma unroll
        for (int cc = 0; cc < 4; cc++) {
            float2 f = *(float2*)&acc[p][cc];
            *(float2*)&out_s[(c0 + cc) * 128 + i0 + 2 * p] = f;
        }
    // reciprocal Z into (now-dead) q_s
    if (tid < 128) q_s[tid] = 1.0f / (z_s[tid * 2] + z_s[tid * 2 + 1]);
    __syncthreads();

    const float gm = gamma[0];
    #pragma unroll
    for (int r = 0; r < 32; r++) {
        int e  = r * 256 + tid;
        int c  = e >> 7;
        int ii = e & 127;
        size_t gi = ((size_t)(b * CH + c)) * NPIX + i0g + ii;
        out[gi] = x[gi] + gm * out_s[e] * q_s[ii];
    }
}

// ---------------------------------------------------------------------------
extern "C" void kernel_launch(void* const* d_in, const int* in_sizes, int n_in,
                              void* d_out, int out_size)
{
    const float* x     = (const float*)d_in[0];
    const float* wq    = (const float*)d_in[1];
    const float* bq    = (const float*)d_in[2];
    const float* wk    = (const float*)d_in[3];
    const float* bk    = (const float*)d_in[4];
    const float* wv    = (const float*)d_in[5];
    const float* bv    = (const float*)d_in[6];
    const float* gamma = (const float*)d_in[7];
    float* out = (float*)d_out;

    cudaFuncSetAttribute(attn_kernel,
                         cudaFuncAttributeMaxDynamicSharedMemorySize,
                         SMEM_BYTES);

    proj_kernel<<<(BATCH * NPIX) / 256, 256>>>(x, wq, bq, wk, bk, wv, bv);
    attn_kernel<<<dim3(NPIX / TQ, BATCH), 256, SMEM_BYTES>>>(x, gamma, out);
}

// round 10
// speedup vs baseline: 1.2602x; 1.2575x over previous
#include <cuda_runtime.h>

typedef unsigned long long ull;

#define BATCH 8
#define CH    64
#define MID   8
#define NPIX  4096
#define TQ    128
#define TJ    64

// Scratch (no allocations allowed -> __device__ globals)
__device__ float g_q[BATCH * NPIX * MID];   // [b][i][m]
__device__ float g_k[BATCH * NPIX * MID];   // [b][j][m]
__device__ float g_v[BATCH * NPIX * CH];    // [b][j][c]

// ---------------------------------------------------------------------------
// Projection kernel: q = Wq x + bq, k = Wk x + bk, v = Wv x + bv  (1x1 convs)
// ---------------------------------------------------------------------------
__global__ __launch_bounds__(256) void proj_kernel(
    const float* __restrict__ x,
    const float* __restrict__ wq, const float* __restrict__ bq,
    const float* __restrict__ wk, const float* __restrict__ bk,
    const float* __restrict__ wv, const float* __restrict__ bv)
{
    __shared__ float s_wvT[CH * CH];     // [c][d]
    __shared__ float s_wqT[CH * MID];    // [c][m]
    __shared__ float s_wkT[CH * MID];    // [c][m]
    __shared__ float s_bq[MID], s_bk[MID], s_bv[CH];

    const int tid = threadIdx.x;
    for (int idx = tid; idx < CH * CH; idx += 256) {
        int d = idx >> 6, c = idx & 63;
        s_wvT[c * CH + d] = wv[idx];
    }
    for (int idx = tid; idx < MID * CH; idx += 256) {
        int m = idx >> 6, c = idx & 63;
        s_wqT[c * MID + m] = wq[idx];
        s_wkT[c * MID + m] = wk[idx];
    }
    if (tid < MID) { s_bq[tid] = bq[tid]; s_bk[tid] = bk[tid]; }
    if (tid < CH)  { s_bv[tid] = bv[tid]; }
    __syncthreads();

    const int g = blockIdx.x * 256 + tid;    // global pixel id = b*NPIX + n
    const int b = g >> 12;
    const int n = g & (NPIX - 1);

    float q[MID], k[MID], v[CH];
    #pragma unroll
    for (int m = 0; m < MID; m++) { q[m] = s_bq[m]; k[m] = s_bk[m]; }
    #pragma unroll
    for (int d = 0; d < CH; d++) v[d] = s_bv[d];

    const float* xp = x + (size_t)b * CH * NPIX + n;
    for (int c = 0; c < CH; c++) {
        float xv = xp[(size_t)c * NPIX];
        #pragma unroll
        for (int m = 0; m < MID; m++) {
            q[m] = fmaf(s_wqT[c * MID + m], xv, q[m]);
            k[m] = fmaf(s_wkT[c * MID + m], xv, k[m]);
        }
        #pragma unroll
        for (int d = 0; d < CH; d++)
            v[d] = fmaf(s_wvT[c * CH + d], xv, v[d]);
    }

    float4* qo = (float4*)&g_q[(size_t)g * MID];
    qo[0] = make_float4(q[0], q[1], q[2], q[3]);
    qo[1] = make_float4(q[4], q[5], q[6], q[7]);
    float4* ko = (float4*)&g_k[(size_t)g * MID];
    ko[0] = make_float4(k[0], k[1], k[2], k[3]);
    ko[1] = make_float4(k[4], k[5], k[6], k[7]);
    float4* vo = (float4*)&g_v[(size_t)g * CH];
    #pragma unroll
    for (int r = 0; r < 16; r++)
        vo[r] = make_float4(v[4 * r], v[4 * r + 1], v[4 * r + 2], v[4 * r + 3]);
}

// ---------------------------------------------------------------------------
// Attention kernel. One block = (batch b, 128-query tile).
// Unnormalized softmax (safe magnitudes in fp32):
//   num[i][c] = sum_j exp(q_i . k_j) * v[c][j],  Z_i = sum_j exp(q_i . k_j)
//   out = x + gamma * num / Z
// GEMM phase: 8i x 8c micro-tile per thread (32 FFMA2/j, 6 LDS.128/j),
// j-range split across the two 128-thread halves; halves summed in epilogue.
// ---------------------------------------------------------------------------
#define FMA_X2(acc, a, bb) \
    asm("fma.rn.f32x2 %0, %1, %2, %0;" : "+l"(acc) : "l"(a), "l"(bb))

// dyn SMEM layout (floats):
//  q_s : [0,      1024)   TQ*8
//  k_s : [1024,   1536)   TJ*8
//  z_s : [1536,   1792)   TQ*2 partial Z
//  e_s : [1792,   9984)   TJ*TQ exp tile  (reused as out staging)
//  v_s : [9984,  18176)   TJ*CH float2 {v,v}
#define SMEM_FLOATS 18176
#define SMEM_BYTES  (SMEM_FLOATS * 4)

__global__ __launch_bounds__(256, 2) void attn_kernel(
    const float* __restrict__ x,
    const float* __restrict__ gamma,
    float* __restrict__ out)
{
    extern __shared__ float smem[];
    float*  q_s = smem;
    float*  k_s = smem + 1024;
    float*  z_s = smem + 1536;
    float*  e_s = smem + 1792;
    float2* v_s = (float2*)(smem + 9984);

    const int tid = threadIdx.x;
    const int b   = blockIdx.y;
    const int i0g = blockIdx.x * TQ;

    // load 128 queries (1024 floats) + zero Z partials
    ((float4*)q_s)[tid] =
        ((const float4*)(g_q + ((size_t)b * NPIX + i0g) * MID))[tid];
    z_s[tid] = 0.0f;
    __syncthreads();

    // E-phase mapping: 1 query per thread, half the j-tile each
    const int il = tid & 127;
    const int jh = tid >> 7;                 // 0 or 1 (also GEMM j-half)
    const float4 qa = ((const float4*)q_s)[il * 2];
    const float4 qb = ((const float4*)q_s)[il * 2 + 1];

    // GEMM mapping: 8 i-rows (4 pairs) x 8 channels per thread, j split by jh
    const int ti = tid & 15;                 // 16 i-groups
    const int tc = (tid >> 4) & 7;           // 8 c-groups
    const int i0 = ti * 8, c0 = tc * 8;

    ull acc[4][8];
    #pragma unroll
    for (int p = 0; p < 4; p++)
        #pragma unroll
        for (int cc = 0; cc < 8; cc++) acc[p][cc] = 0ull;

    const float* kg_base = g_k + (size_t)b * NPIX * MID;
    const float* vg_base = g_v + (size_t)b * NPIX * CH;

    for (int jt = 0; jt < NPIX / TJ; jt++) {
        const int j0 = jt * TJ;
        __syncthreads();  // previous GEMM done reading e_s/v_s

        if (tid < 128)
            ((float4*)k_s)[tid] = ((const float4*)(kg_base + (size_t)j0 * MID))[tid];
        const float* vg = vg_base + (size_t)j0 * CH;
        #pragma unroll
        for (int r = 0; r < 16; r++) {
            int idx = r * 256 + tid;
            float vv = vg[idx];
            v_s[idx] = make_float2(vv, vv);
        }
        __syncthreads();

        // ---- E phase: e = exp(q.k), accumulate partial Z ----
        float zloc = 0.0f;
        #pragma unroll 4
        for (int jj = 0; jj < 32; jj++) {
            int j = jh * 32 + jj;
            float4 ka = ((const float4*)k_s)[j * 2];
            float4 kb = ((const float4*)k_s)[j * 2 + 1];
            float s = qa.x * ka.x + qa.y * ka.y + qa.z * ka.z + qa.w * ka.w
                    + qb.x * kb.x + qb.y * kb.y + qb.z * kb.z + qb.w * kb.w;
            float e = __expf(s);
            zloc += e;
            e_s[j * 128 + il] = e;
        }
        z_s[il * 2 + jh] += zloc;   // unique owner per (il, jh)
        __syncthreads();

        // ---- GEMM phase: acc += E_pair * {v,v}  (packed f32x2) ----
        // this half handles j in [jh*32, jh*32+32)
        #pragma unroll 2
        for (int jj = 0; jj < 32; jj++) {
            int j = jh * 32 + jj;
            const float* er = &e_s[j * 128 + i0];
            ulonglong2 eA = *(const ulonglong2*)er;          // i0..i0+3
            ulonglong2 eB = *(const ulonglong2*)(er + 4);    // i0+4..i0+7
            const ull* vr = (const ull*)&v_s[j * 64 + c0];
            ulonglong2 v01 = *(const ulonglong2*)(vr + 0);   // ch c0,c0+1 dup'd
            ulonglong2 v23 = *(const ulonglong2*)(vr + 2);
            ulonglong2 v45 = *(const ulonglong2*)(vr + 4);
            ulonglong2 v67 = *(const ulonglong2*)(vr + 6);

            FMA_X2(acc[0][0], eA.x, v01.x); FMA_X2(acc[0][1], eA.x, v01.y);
            FMA_X2(acc[0][2], eA.x, v23.x); FMA_X2(acc[0][3], eA.x, v23.y);
            FMA_X2(acc[0][4], eA.x, v45.x); FMA_X2(acc[0][5], eA.x, v45.y);
            FMA_X2(acc[0][6], eA.x, v67.x); FMA_X2(acc[0][7], eA.x, v67.y);

            FMA_X2(acc[1][0], eA.y, v01.x); FMA_X2(acc[1][1], eA.y, v01.y);
            FMA_X2(acc[1][2], eA.y, v23.x); FMA_X2(acc[1][3], eA.y, v23.y);
            FMA_X2(acc[1][4], eA.y, v45.x); FMA_X2(acc[1][5], eA.y, v45.y);
            FMA_X2(acc[1][6], eA.y, v67.x); FMA_X2(acc[1][7], eA.y, v67.y);

            FMA_X2(acc[2][0], eB.x, v01.x); FMA_X2(acc[2][1], eB.x, v01.y);
            FMA_X2(acc[2][2], eB.x, v23.x); FMA_X2(acc[2][3], eB.x, v23.y);
            FMA_X2(acc[2][4], eB.x, v45.x); FMA_X2(acc[2][5], eB.x, v45.y);
            FMA_X2(acc[2][6], eB.x, v67.x); FMA_X2(acc[2][7], eB.x, v67.y);

            FMA_X2(acc[3][0], eB.y, v01.x); FMA_X2(acc[3][1], eB.y, v01.y);
            FMA_X2(acc[3][2], eB.y, v23.x); FMA_X2(acc[3][3], eB.y, v23.y);
            FMA_X2(acc[3][4], eB.y, v45.x); FMA_X2(acc[3][5], eB.y, v45.y);
            FMA_X2(acc[3][6], eB.y, v67.x); FMA_X2(acc[3][7], eB.y, v67.y);
        }
    }
    __syncthreads();   // all GEMM reads of e_s done -> reuse as out staging

    // combine the two j-halves through SMEM: out_s[c][i], 64*128 floats
    float* out_s = e_s;
    if (jh == 1) {
        #pragma unroll
        for (int cc = 0; cc < 8; cc++)
            #pragma unroll
            for (int p = 0; p < 4; p++)
                *(float2*)&out_s[(c0 + cc) * 128 + i0 + 2 * p] =
                    *(float2*)&acc[p][cc];
    }
    __syncthreads();
    if (jh == 0) {
        #pragma unroll
        for (int cc = 0; cc < 8; cc++)
            #pragma unroll
            for (int p = 0; p < 4; p++) {
                float2* dst = (float2*)&out_s[(c0 + cc) * 128 + i0 + 2 * p];
                float2 t = *dst;
                float2 a = *(float2*)&acc[p][cc];
                t.x += a.x; t.y += a.y;
                *dst = t;
            }
    }
    // reciprocal Z into (now-dead) q_s
    if (tid < 128) q_s[tid] = 1.0f / (z_s[tid * 2] + z_s[tid * 2 + 1]);
    __syncthreads();

    const float gm = gamma[0];
    #pragma unroll
    for (int r = 0; r < 32; r++) {
        int e  = r * 256 + tid;
        int c  = e >> 7;
        int ii = e & 127;
        size_t gi = ((size_t)(b * CH + c)) * NPIX + i0g + ii;
        out[gi] = x[gi] + gm * out_s[e] * q_s[ii];
    }
}

// ---------------------------------------------------------------------------
extern "C" void kernel_launch(void* const* d_in, const int* in_sizes, int n_in,
                              void* d_out, int out_size)
{
    const float* x     = (const float*)d_in[0];
    const float* wq    = (const float*)d_in[1];
    const float* bq    = (const float*)d_in[2];
    const float* wk    = (const float*)d_in[3];
    const float* bk    = (const float*)d_in[4];
    const float* wv    = (const float*)d_in[5];
    const float* bv    = (const float*)d_in[6];
    const float* gamma = (const float*)d_in[7];
    float* out = (float*)d_out;

    cudaFuncSetAttribute(attn_kernel,
                         cudaFuncAttributeMaxDynamicSharedMemorySize,
                         SMEM_BYTES);

    proj_kernel<<<(BATCH * NPIX) / 256, 256>>>(x, wq, bq, wk, bk, wv, bv);
    attn_kernel<<<dim3(NPIX / TQ, BATCH), 256, SMEM_BYTES>>>(x, gamma, out);
}

// round 12
// speedup vs baseline: 3.9862x; 3.1632x over previous
#include <cuda_runtime.h>
#include <cstdint>

#define BATCH 8
#define CH    64
#define MID   8
#define NPIX  4096
#define TQ    128
#define TJ    64
#define NCH   72            // 64 real channels + 8 "ones" columns for Z

// Scratch (no allocations allowed -> __device__ globals)
__device__ float g_q[BATCH * NPIX * MID];   // [b][i][m]
__device__ float g_k[BATCH * NPIX * MID];   // [b][j][m]
__device__ float g_v[BATCH * NPIX * CH];    // [b][j][c]

// ---------------------------------------------------------------------------
// helpers
// ---------------------------------------------------------------------------
__device__ __forceinline__ uint32_t smem_u32(const void* p) {
    uint32_t a;
    asm("{ .reg .u64 t; cvta.to.shared.u64 t, %1; cvt.u32.u64 %0, t; }"
        : "=r"(a) : "l"(p));
    return a;
}
__device__ __forceinline__ void cp_async16(uint32_t dst, const void* src) {
    asm volatile("cp.async.cg.shared.global [%0], [%1], 16;"
                 :: "r"(dst), "l"(src) : "memory");
}
#define CP_COMMIT()  asm volatile("cp.async.commit_group;" ::: "memory")
#define CP_WAIT0()   asm volatile("cp.async.wait_group 0;" ::: "memory")

__device__ __forceinline__ uint32_t f2tf32(float f) {
    uint32_t u;
    asm("cvt.rna.tf32.f32 %0, %1;" : "=r"(u) : "f"(f));
    return u;
}

// m16n8k8 tf32 MMA: D(16x8,f32) += A(16x8,tf32,row) * B(8x8,tf32,col)
__device__ __forceinline__ void mma_tf32(float* d,
                                         uint32_t a0, uint32_t a1,
                                         uint32_t a2, uint32_t a3,
                                         uint32_t b0, uint32_t b1) {
    asm volatile(
        "mma.sync.aligned.m16n8k8.row.col.f32.tf32.tf32.f32 "
        "{%0,%1,%2,%3}, {%4,%5,%6,%7}, {%8,%9}, {%0,%1,%2,%3};"
        : "+f"(d[0]), "+f"(d[1]), "+f"(d[2]), "+f"(d[3])
        : "r"(a0), "r"(a1), "r"(a2), "r"(a3), "r"(b0), "r"(b1));
}

// ---------------------------------------------------------------------------
// Projection kernel: q/k [b][n][8], v [b][n][64]
// ---------------------------------------------------------------------------
__global__ __launch_bounds__(256) void proj_kernel(
    const float* __restrict__ x,
    const float* __restrict__ wq, const float* __restrict__ bq,
    const float* __restrict__ wk, const float* __restrict__ bk,
    const float* __restrict__ wv, const float* __restrict__ bv)
{
    __shared__ float s_wvT[CH * CH];
    __shared__ float s_wqT[CH * MID];
    __shared__ float s_wkT[CH * MID];
    __shared__ float s_bq[MID], s_bk[MID], s_bv[CH];

    const int tid = threadIdx.x;
    for (int idx = tid; idx < CH * CH; idx += 256) {
        int d = idx >> 6, c = idx & 63;
        s_wvT[c * CH + d] = wv[idx];
    }
    for (int idx = tid; idx < MID * CH; idx += 256) {
        int m = idx >> 6, c = idx & 63;
        s_wqT[c * MID + m] = wq[idx];
        s_wkT[c * MID + m] = wk[idx];
    }
    if (tid < MID) { s_bq[tid] = bq[tid]; s_bk[tid] = bk[tid]; }
    if (tid < CH)  { s_bv[tid] = bv[tid]; }
    __syncthreads();

    const int g = blockIdx.x * 256 + tid;    // b*NPIX + n
    const int b = g >> 12;
    const int n = g & (NPIX - 1);

    float q[MID], k[MID], v[CH];
    #pragma unroll
    for (int m = 0; m < MID; m++) { q[m] = s_bq[m]; k[m] = s_bk[m]; }
    #pragma unroll
    for (int d = 0; d < CH; d++) v[d] = s_bv[d];

    const float* xp = x + (size_t)b * CH * NPIX + n;
    for (int c = 0; c < CH; c++) {
        float xv = xp[(size_t)c * NPIX];
        #pragma unroll
        for (int m = 0; m < MID; m++) {
            q[m] = fmaf(s_wqT[c * MID + m], xv, q[m]);
            k[m] = fmaf(s_wkT[c * MID + m], xv, k[m]);
        }
        #pragma unroll
        for (int d = 0; d < CH; d++)
            v[d] = fmaf(s_wvT[c * CH + d], xv, v[d]);
    }

    float4* qo = (float4*)&g_q[(size_t)g * MID];
    qo[0] = make_float4(q[0], q[1], q[2], q[3]);
    qo[1] = make_float4(q[4], q[5], q[6], q[7]);
    float4* ko = (float4*)&g_k[(size_t)g * MID];
    ko[0] = make_float4(k[0], k[1], k[2], k[3]);
    ko[1] = make_float4(k[4], k[5], k[6], k[7]);
    float4* vo = (float4*)&g_v[(size_t)g * CH];
    #pragma unroll
    for (int r = 0; r < 16; r++)
        vo[r] = make_float4(v[4 * r], v[4 * r + 1], v[4 * r + 2], v[4 * r + 3]);
}

// ---------------------------------------------------------------------------
// Attention kernel: mma.sync tf32 for PV + Z.
// Block = (b, 128-query tile). Warp w owns i-rows [16w, 16w+16).
// A-fragment e-values computed in registers (q regs + k from SMEM).
// B-fragments read from SMEM V tile [64j x 72c] (cols 64..71 == 1 -> Z).
// ---------------------------------------------------------------------------
// dyn SMEM (floats):
//   buf0: V0 @0     (64*72=4608), K0 @4608 (512)  -> 5120
//   buf1: V1 @5120,               K1 @9728        -> 10240
//   z_s @10240 (128)
//   epilogue staging out_s[64][129] @0 (8256, reuses buffers)
#define VOFF0 0
#define KOFF0 4608
#define VOFF1 5120
#define KOFF1 9728
#define ZOFF  10240
#define SMEM_FLOATS 10368
#define SMEM_BYTES  (SMEM_FLOATS * 4)

__device__ __forceinline__ void prefetch_tile(uint32_t sm, int bufV, int bufK,
                                              const float* vg, const float* kg,
                                              int tid)
{
    // V tile: 64 rows x 64 floats -> smem rows stride 72 floats
    #pragma unroll
    for (int u = 0; u < 4; u++) {
        int idx = u * 256 + tid;            // 0..1023 float4s
        int j = idx >> 4, c4 = (idx & 15) << 2;
        cp_async16(sm + (uint32_t)(bufV + j * NCH + c4) * 4, vg + j * CH + c4);
    }
    // K tile: 64 x 8 floats = 128 float4
    if (tid < 128)
        cp_async16(sm + (uint32_t)(bufK + tid * 4) * 4, kg + tid * 4);
}

__global__ __launch_bounds__(256, 2) void attn_kernel(
    const float* __restrict__ x,
    const float* __restrict__ gamma,
    float* __restrict__ out)
{
    extern __shared__ __align__(128) float smem[];
    const uint32_t sm = smem_u32(smem);
    const int tid = threadIdx.x;
    const int wid = tid >> 5;
    const int lid = tid & 31;
    const int g8  = lid >> 2;        // groupID 0..7
    const int tig = lid & 3;         // thread-in-group 0..3
    const int b   = blockIdx.y;
    const int i0g = blockIdx.x * TQ;

    // ones columns (channels 64..71) of both V buffers
    for (int idx = tid; idx < 1024; idx += 256) {
        int bf = idx >> 9;           // 0 / 1
        int r  = idx & 511;
        int j  = r >> 3, c = 64 + (r & 7);
        smem[(bf ? VOFF1 : VOFF0) + j * NCH + c] = 1.0f;
    }

    // register-resident q for this thread's two fragment rows
    const int ia = i0g + wid * 16 + g8;
    const float4 qa0 = ((const float4*)(g_q + ((size_t)b * NPIX + ia) * MID))[0];
    const float4 qa1 = ((const float4*)(g_q + ((size_t)b * NPIX + ia) * MID))[1];
    const float4 qb0 = ((const float4*)(g_q + ((size_t)b * NPIX + ia + 8) * MID))[0];
    const float4 qb1 = ((const float4*)(g_q + ((size_t)b * NPIX + ia + 8) * MID))[1];

    float acc[9][4];
    #pragma unroll
    for (int n = 0; n < 9; n++)
        #pragma unroll
        for (int r = 0; r < 4; r++) acc[n][r] = 0.0f;

    const float* vb = g_v + (size_t)b * NPIX * CH;
    const float* kb = g_k + (size_t)b * NPIX * MID;
    const uint32_t ONEF = 0x3f800000u;

    prefetch_tile(sm, VOFF0, KOFF0, vb, kb, tid);
    CP_COMMIT();

    for (int t = 0; t < NPIX / TJ; t++) {
        CP_WAIT0();
        __syncthreads();
        if (t + 1 < NPIX / TJ) {
            const int j0n = (t + 1) * TJ;
            prefetch_tile(sm, (t & 1) ? VOFF0 : VOFF1, (t & 1) ? KOFF0 : KOFF1,
                          vb + (size_t)j0n * CH, kb + (size_t)j0n * MID, tid);
            CP_COMMIT();
        }
        const float*  vs  = smem + ((t & 1) ? VOFF1 : VOFF0);
        const float4* ks4 = (const float4*)(smem + ((t & 1) ? KOFF1 : KOFF0));

        #pragma unroll
        for (int c8 = 0; c8 < 8; c8++) {
            const int j1 = c8 * 8 + tig;
            const int j2 = j1 + 4;
            float4 k1a = ks4[j1 * 2], k1b = ks4[j1 * 2 + 1];
            float4 k2a = ks4[j2 * 2], k2b = ks4[j2 * 2 + 1];

            float s0 = qa0.x*k1a.x + qa0.y*k1a.y + qa0.z*k1a.z + qa0.w*k1a.w
                     + qa1.x*k1b.x + qa1.y*k1b.y + qa1.z*k1b.z + qa1.w*k1b.w;
            float s1 = qb0.x*k1a.x + qb0.y*k1a.y + qb0.z*k1a.z + qb0.w*k1a.w
                     + qb1.x*k1b.x + qb1.y*k1b.y + qb1.z*k1b.z + qb1.w*k1b.w;
            float s2 = qa0.x*k2a.x + qa0.y*k2a.y + qa0.z*k2a.z + qa0.w*k2a.w
                     + qa1.x*k2b.x + qa1.y*k2b.y + qa1.z*k2b.z + qa1.w*k2b.w;
            float s3 = qb0.x*k2a.x + qb0.y*k2a.y + qb0.z*k2a.z + qb0.w*k2a.w
                     + qb1.x*k2b.x + qb1.y*k2b.y + qb1.z*k2b.z + qb1.w*k2b.w;

            // A fragment (m16n8k8 tf32, row-major):
            //   a0:(g, j1) a1:(g+8, j1) a2:(g, j2) a3:(g+8, j2)
            uint32_t a0 = f2tf32(__expf(s0));
            uint32_t a1 = f2tf32(__expf(s1));
            uint32_t a2 = f2tf32(__expf(s2));
            uint32_t a3 = f2tf32(__expf(s3));

            const float* b1p = vs + j1 * NCH + g8;
            const float* b2p = vs + j2 * NCH + g8;
            #pragma unroll
            for (int ng = 0; ng < 8; ng++) {
                uint32_t b0 = __float_as_uint(b1p[ng * 8]);
                uint32_t b1 = __float_as_uint(b2p[ng * 8]);
                mma_tf32(acc[ng], a0, a1, a2, a3, b0, b1);
            }
            // Z group: B == ones (no LDS needed)
            mma_tf32(acc[8], a0, a1, a2, a3, ONEF, ONEF);
        }
        __syncthreads();
    }

    // ---- epilogue: stage fragments, normalize, coalesced writes ----
    float* out_s = smem;          // [64][129]
    float* z_s   = smem + ZOFF;   // [128]

    #pragma unroll
    for (int ng = 0; ng < 8; ng++) {
        int c = ng * 8 + 2 * tig;
        int i = wid * 16 + g8;
        out_s[c * 129 + i]             = acc[ng][0];
        out_s[(c + 1) * 129 + i]       = acc[ng][1];
        out_s[c * 129 + i + 8]         = acc[ng][2];
        out_s[(c + 1) * 129 + i + 8]   = acc[ng][3];
    }
    z_s[wid * 16 + g8]     = acc[8][0];
    z_s[wid * 16 + g8 + 8] = acc[8][2];
    __syncthreads();
    if (tid < 128) z_s[tid] = 1.0f / z_s[tid];
    __syncthreads();

    const float gm = gamma[0];
    #pragma unroll
    for (int r = 0; r < 32; r++) {
        int e  = r * 256 + tid;
        int c  = e >> 7;
        int ii = e & 127;
        size_t gi = ((size_t)(b * CH + c)) * NPIX + i0g + ii;
        out[gi] = fmaf(gm * out_s[c * 129 + ii], z_s[ii], x[gi]);
    }
}

// ---------------------------------------------------------------------------
extern "C" void kernel_launch(void* const* d_in, const int* in_sizes, int n_in,
                              void* d_out, int out_size)
{
    const float* x     = (const float*)d_in[0];
    const float* wq    = (const float*)d_in[1];
    const float* bq    = (const float*)d_in[2];
    const float* wk    = (const float*)d_in[3];
    const float* bk    = (const float*)d_in[4];
    const float* wv    = (const float*)d_in[5];
    const float* bv    = (const float*)d_in[6];
    const float* gamma = (const float*)d_in[7];
    float* out = (float*)d_out;

    cudaFuncSetAttribute(attn_kernel,
                         cudaFuncAttributeMaxDynamicSharedMemorySize,
                         SMEM_BYTES);

    proj_kernel<<<(BATCH * NPIX) / 256, 256>>>(x, wq, bq, wk, bk, wv, bv);
    attn_kernel<<<dim3(NPIX / TQ, BATCH), 256, SMEM_BYTES>>>(x, gamma, out);
}

// round 13
// speedup vs baseline: 5.7179x; 1.4344x over previous
#include <cuda_runtime.h>
#include <cstdint>

#define BATCH 8
#define CH    64
#define MID   8
#define NPIX  4096
#define TQ    128
#define TJ    64
#define VSTR  72            // V smem row stride (64 j + 8 pad)

// Scratch (no allocations allowed -> __device__ globals)
__device__ float g_q[BATCH * NPIX * MID];   // [b][i][m]  (pre-scaled by log2e, tf32-rounded)
__device__ float g_k[BATCH * NPIX * MID];   // [b][j][m'] m interleaved (0,4,1,5,2,6,3,7), tf32-rounded
__device__ float g_v[BATCH * CH * NPIX];    // TRANSPOSED [b][c][n]

// ---------------------------------------------------------------------------
// helpers
// ---------------------------------------------------------------------------
__device__ __forceinline__ uint32_t smem_u32(const void* p) {
    uint32_t a;
    asm("{ .reg .u64 t; cvta.to.shared.u64 t, %1; cvt.u32.u64 %0, t; }"
        : "=r"(a) : "l"(p));
    return a;
}
__device__ __forceinline__ void cp_async16(uint32_t dst, const void* src) {
    asm volatile("cp.async.cg.shared.global [%0], [%1], 16;"
                 :: "r"(dst), "l"(src) : "memory");
}
#define CP_COMMIT()  asm volatile("cp.async.commit_group;" ::: "memory")
#define CP_WAIT0()   asm volatile("cp.async.wait_group 0;" ::: "memory")

__device__ __forceinline__ float f2tf32r(float f) {
    uint32_t u;
    asm("cvt.rna.tf32.f32 %0, %1;" : "=r"(u) : "f"(f));
    return __uint_as_float(u);
}
__device__ __forceinline__ float ex2(float f) {
    float r;
    asm("ex2.approx.f32 %0, %1;" : "=f"(r) : "f"(f));
    return r;
}

// m16n8k8 tf32 MMA: D(16x8,f32) += A(16x8,tf32,row) * B(8x8,tf32,col)
__device__ __forceinline__ void mma_tf32(float* d,
                                         uint32_t a0, uint32_t a1,
                                         uint32_t a2, uint32_t a3,
                                         uint32_t b0, uint32_t b1) {
    asm volatile(
        "mma.sync.aligned.m16n8k8.row.col.f32.tf32.tf32.f32 "
        "{%0,%1,%2,%3}, {%4,%5,%6,%7}, {%8,%9}, {%0,%1,%2,%3};"
        : "+f"(d[0]), "+f"(d[1]), "+f"(d[2]), "+f"(d[3])
        : "r"(a0), "r"(a1), "r"(a2), "r"(a3), "r"(b0), "r"(b1));
}

// ---------------------------------------------------------------------------
// Projection kernel
//   q' = tf32_rna(log2e * (Wq x + bq))       [b][n][m]
//   k' = tf32_rna(Wk x + bk), m-interleaved  [b][n][0,4,1,5,2,6,3,7]
//   v  = Wv x + bv, transposed               [b][c][n]
// ---------------------------------------------------------------------------
__global__ __launch_bounds__(256) void proj_kernel(
    const float* __restrict__ x,
    const float* __restrict__ wq, const float* __restrict__ bq,
    const float* __restrict__ wk, const float* __restrict__ bk,
    const float* __restrict__ wv, const float* __restrict__ bv)
{
    __shared__ float s_wvT[CH * CH];
    __shared__ float s_wqT[CH * MID];
    __shared__ float s_wkT[CH * MID];
    __shared__ float s_bq[MID], s_bk[MID], s_bv[CH];

    const int tid = threadIdx.x;
    for (int idx = tid; idx < CH * CH; idx += 256) {
        int d = idx >> 6, c = idx & 63;
        s_wvT[c * CH + d] = wv[idx];
    }
    for (int idx = tid; idx < MID * CH; idx += 256) {
        int m = idx >> 6, c = idx & 63;
        s_wqT[c * MID + m] = wq[idx];
        s_wkT[c * MID + m] = wk[idx];
    }
    if (tid < MID) { s_bq[tid] = bq[tid]; s_bk[tid] = bk[tid]; }
    if (tid < CH)  { s_bv[tid] = bv[tid]; }
    __syncthreads();

    const int g = blockIdx.x * 256 + tid;    // b*NPIX + n
    const int b = g >> 12;
    const int n = g & (NPIX - 1);

    float q[MID], k[MID], v[CH];
    #pragma unroll
    for (int m = 0; m < MID; m++) { q[m] = s_bq[m]; k[m] = s_bk[m]; }
    #pragma unroll
    for (int d = 0; d < CH; d++) v[d] = s_bv[d];

    const float* xp = x + (size_t)b * CH * NPIX + n;
    for (int c = 0; c < CH; c++) {
        float xv = xp[(size_t)c * NPIX];
        #pragma unroll
        for (int m = 0; m < MID; m++) {
            q[m] = fmaf(s_wqT[c * MID + m], xv, q[m]);
            k[m] = fmaf(s_wkT[c * MID + m], xv, k[m]);
        }
        #pragma unroll
        for (int d = 0; d < CH; d++)
            v[d] = fmaf(s_wvT[c * CH + d], xv, v[d]);
    }

    const float LOG2E = 1.4426950408889634f;
    #pragma unroll
    for (int m = 0; m < MID; m++) {
        q[m] = f2tf32r(q[m] * LOG2E);
        k[m] = f2tf32r(k[m]);
    }

    float4* qo = (float4*)&g_q[(size_t)g * MID];
    qo[0] = make_float4(q[0], q[1], q[2], q[3]);
    qo[1] = make_float4(q[4], q[5], q[6], q[7]);
    // K interleaved: pos 2t = m t, pos 2t+1 = m t+4
    float4* ko = (float4*)&g_k[(size_t)g * MID];
    ko[0] = make_float4(k[0], k[4], k[1], k[5]);
    ko[1] = make_float4(k[2], k[6], k[3], k[7]);
    // V transposed (lane-consecutive n -> coalesced)
    #pragma unroll
    for (int d = 0; d < CH; d++)
        g_v[((size_t)(b * CH + d)) * NPIX + n] = v[d];
}

// ---------------------------------------------------------------------------
// Attention kernel — all GEMMs on mma.sync tf32.
// Block = (b, 128-query tile); warp w owns i-rows [16w, 16w+16).
// Per 64-j tile, per warp:
//   S-MMA x8 (A=q regs, B=K_s interleaved -> LDS.64)
//   exp2 on S frags (q pre-scaled by log2e)
//   PV-MMA x72 with k-permutation: A slots (t,t+4) <-> j-cols (2t,2t+1),
//     so D-frag regs (s0,s2,s1,s3) feed A directly (no shuffles) and
//     B-frags are adjacent V rows -> LDS.64 from c-major V_s (stride 72).
//   Z via ones-constant MMA (b0=b1=1.0).
// ---------------------------------------------------------------------------
// dyn SMEM (floats):
//   V0 @0 (64*72=4608), K0 @4608 (512) | V1 @5120, K1 @9728 | z @10240
//   epilogue staging out_s[64][129] @0 (reuses buffers)
#define VOFF0 0
#define KOFF0 4608
#define VOFF1 5120
#define KOFF1 9728
#define ZOFF  10240
#define SMEM_FLOATS 10368
#define SMEM_BYTES  (SMEM_FLOATS * 4)

__device__ __forceinline__ void prefetch_tile(uint32_t sm, int bufV, int bufK,
                                              const float* vg, const float* kg,
                                              int j0, int tid)
{
    // V tile: 64 c-rows x 64 j floats, smem row stride VSTR
    #pragma unroll
    for (int u = 0; u < 4; u++) {
        int ck = u * 256 + tid;           // 0..1023
        int c = ck >> 4, j4 = (ck & 15) << 2;
        cp_async16(sm + (uint32_t)(bufV + c * VSTR + j4) * 4,
                   vg + (size_t)c * NPIX + j0 + j4);
    }
    // K tile: 64 x 8 floats = 128 float4
    if (tid < 128) {
        int j = tid >> 1, h = (tid & 1) << 2;
        cp_async16(sm + (uint32_t)(bufK + j * 8 + h) * 4,
                   kg + (size_t)(j0 + j) * MID + h);
    }
}

__global__ __launch_bounds__(256, 2) void attn_kernel(
    const float* __restrict__ x,
    const float* __restrict__ gamma,
    float* __restrict__ out)
{
    extern __shared__ __align__(128) float smem[];
    const uint32_t sm = smem_u32(smem);
    const int tid = threadIdx.x;
    const int wid = tid >> 5;
    const int lid = tid & 31;
    const int g8  = lid >> 2;        // groupID 0..7
    const int tig = lid & 3;         // thread-in-group 0..3
    const int b   = blockIdx.y;
    const int i0g = blockIdx.x * TQ;

    // q A-fragment registers (m-order: slots t, t+4 = logical m tig, tig+4)
    const int ia = i0g + wid * 16 + g8;
    const float* qp  = g_q + ((size_t)b * NPIX + ia) * MID;
    const uint32_t qA0 = __float_as_uint(qp[tig]);
    const uint32_t qA1 = __float_as_uint(qp[8 * MID + tig]);
    const uint32_t qA2 = __float_as_uint(qp[tig + 4]);
    const uint32_t qA3 = __float_as_uint(qp[8 * MID + tig + 4]);

    float acc[8][4];
    float accz[4];
    #pragma unroll
    for (int ng = 0; ng < 8; ng++)
        #pragma unroll
        for (int r = 0; r < 4; r++) acc[ng][r] = 0.0f;
    #pragma unroll
    for (int r = 0; r < 4; r++) accz[r] = 0.0f;

    const float* vb = g_v + (size_t)(b * CH) * NPIX;
    const float* kb = g_k + (size_t)b * NPIX * MID;
    const uint32_t ONEF = 0x3f800000u;

    prefetch_tile(sm, VOFF0, KOFF0, vb, kb, 0, tid);
    CP_COMMIT();

    for (int t = 0; t < NPIX / TJ; t++) {
        CP_WAIT0();
        __syncthreads();
        if (t + 1 < NPIX / TJ) {
            prefetch_tile(sm, (t & 1) ? VOFF0 : VOFF1,
                          (t & 1) ? KOFF0 : KOFF1,
                          vb, kb, (t + 1) * TJ, tid);
            CP_COMMIT();
        }
        const float* vs = smem + ((t & 1) ? VOFF1 : VOFF0);
        const float* ks = smem + ((t & 1) ? KOFF1 : KOFF0);

        #pragma unroll
        for (int jn = 0; jn < 8; jn++) {
            // ---- S-MMA: S(i, jb + 0..7), B-frag = interleaved K row ----
            float2 kf = *(const float2*)&ks[(jn * 8 + g8) * 8 + 2 * tig];
            float s[4] = {0.0f, 0.0f, 0.0f, 0.0f};
            mma_tf32(s, qA0, qA1, qA2, qA3,
                     __float_as_uint(kf.x), __float_as_uint(kf.y));

            // exp2 (q pre-scaled by log2e). D-frag -> A-frag by renaming:
            //   slot t   <-> j col 2t   : (s0, s2)
            //   slot t+4 <-> j col 2t+1 : (s1, s3)
            uint32_t a0 = __float_as_uint(ex2(s[0]));
            uint32_t a1 = __float_as_uint(ex2(s[2]));
            uint32_t a2 = __float_as_uint(ex2(s[1]));
            uint32_t a3 = __float_as_uint(ex2(s[3]));

            const int jb = jn * 8;
            const float* vrow = vs + jb + 2 * tig;
            #pragma unroll
            for (int ng = 0; ng < 8; ng++) {
                float2 vv = *(const float2*)&vrow[(ng * 8 + g8) * VSTR];
                mma_tf32(acc[ng], a0, a1, a2, a3,
                         __float_as_uint(vv.x), __float_as_uint(vv.y));
            }
            mma_tf32(accz, a0, a1, a2, a3, ONEF, ONEF);
        }
        __syncthreads();
    }

    // ---- epilogue: stage fragments, normalize, coalesced writes ----
    float* out_s = smem;          // [64][129]
    float* z_s   = smem + ZOFF;   // [128]

    #pragma unroll
    for (int ng = 0; ng < 8; ng++) {
        int c = ng * 8 + 2 * tig;
        int i = wid * 16 + g8;
        out_s[c * 129 + i]           = acc[ng][0];
        out_s[(c + 1) * 129 + i]     = acc[ng][1];
        out_s[c * 129 + i + 8]       = acc[ng][2];
        out_s[(c + 1) * 129 + i + 8] = acc[ng][3];
    }
    z_s[wid * 16 + g8]     = accz[0];
    z_s[wid * 16 + g8 + 8] = accz[2];
    __syncthreads();
    if (tid < 128) z_s[tid] = 1.0f / z_s[tid];
    __syncthreads();

    const float gm = gamma[0];
    #pragma unroll
    for (int r = 0; r < 32; r++) {
        int e  = r * 256 + tid;
        int c  = e >> 7;
        int ii = e & 127;
        size_t gi = ((size_t)(b * CH + c)) * NPIX + i0g + ii;
        out[gi] = fmaf(gm * out_s[c * 129 + ii], z_s[ii], x[gi]);
    }
}

// ---------------------------------------------------------------------------
extern "C" void kernel_launch(void* const* d_in, const int* in_sizes, int n_in,
                              void* d_out, int out_size)
{
    const float* x     = (const float*)d_in[0];
    const float* wq    = (const float*)d_in[1];
    const float* bq    = (const float*)d_in[2];
    const float* wk    = (const float*)d_in[3];
    const float* bk    = (const float*)d_in[4];
    const float* wv    = (const float*)d_in[5];
    const float* bv    = (const float*)d_in[6];
    const float* gamma = (const float*)d_in[7];
    float* out = (float*)d_out;

    cudaFuncSetAttribute(attn_kernel,
                         cudaFuncAttributeMaxDynamicSharedMemorySize,
                         SMEM_BYTES);

    proj_kernel<<<(BATCH * NPIX) / 256, 256>>>(x, wq, bq, wk, bk, wv, bv);
    attn_kernel<<<dim3(NPIX / TQ, BATCH), 256, SMEM_BYTES>>>(x, gamma, out);
}

// round 15
// speedup vs baseline: 8.2073x; 1.4354x over previous
#include <cuda_runtime.h>
#include <cuda_fp16.h>
#include <cstdint>

typedef unsigned long long ull;

#define BATCH 8
#define CH    64
#define MID   8
#define NPIX  4096
#define TQ    128
#define TJ    64
#define VSTR  72            // V smem row stride in halves (64 j + 8 pad)

// Scratch (no allocations allowed -> __device__ globals)
__device__ float  g_q[BATCH * NPIX * MID];  // [b][i][m] pre-scaled by log2e, tf32-rounded
__device__ float  g_k[BATCH * NPIX * MID];  // [b][j][m'] m interleaved (0,4,1,5,2,6,3,7)
__device__ __half g_v[BATCH * CH * NPIX];   // TRANSPOSED [b][c][n], fp16

// ---------------------------------------------------------------------------
// helpers
// ---------------------------------------------------------------------------
__device__ __forceinline__ uint32_t smem_u32(const void* p) {
    uint32_t a;
    asm("{ .reg .u64 t; cvta.to.shared.u64 t, %1; cvt.u32.u64 %0, t; }"
        : "=r"(a) : "l"(p));
    return a;
}
__device__ __forceinline__ void cp_async16(uint32_t dst, const void* src) {
    asm volatile("cp.async.cg.shared.global [%0], [%1], 16;"
                 :: "r"(dst), "l"(src) : "memory");
}
#define CP_COMMIT()  asm volatile("cp.async.commit_group;" ::: "memory")
#define CP_WAIT0()   asm volatile("cp.async.wait_group 0;" ::: "memory")

__device__ __forceinline__ float f2tf32r(float f) {
    uint32_t u;
    asm("cvt.rna.tf32.f32 %0, %1;" : "=r"(u) : "f"(f));
    return __uint_as_float(u);
}
__device__ __forceinline__ float ex2(float f) {
    float r;
    asm("ex2.approx.f32 %0, %1;" : "=f"(r) : "f"(f));
    return r;
}
// pack two f32 -> f16x2 (lo = first arg, hi = second)
__device__ __forceinline__ uint32_t packh(float lo, float hi) {
    uint32_t d;
    asm("cvt.rn.f16x2.f32 %0, %1, %2;" : "=r"(d) : "f"(hi), "f"(lo));
    return d;
}

// m16n8k8 tf32 MMA (for S): D += A * B
__device__ __forceinline__ void mma_tf32(float* d,
                                         uint32_t a0, uint32_t a1,
                                         uint32_t a2, uint32_t a3,
                                         uint32_t b0, uint32_t b1) {
    asm volatile(
        "mma.sync.aligned.m16n8k8.row.col.f32.tf32.tf32.f32 "
        "{%0,%1,%2,%3}, {%4,%5,%6,%7}, {%8,%9}, {%0,%1,%2,%3};"
        : "+f"(d[0]), "+f"(d[1]), "+f"(d[2]), "+f"(d[3])
        : "r"(a0), "r"(a1), "r"(a2), "r"(a3), "r"(b0), "r"(b1));
}
// m16n8k16 fp16 MMA with f32 accum (for PV / Z)
__device__ __forceinline__ void mma_f16(float* d,
                                        uint32_t a0, uint32_t a1,
                                        uint32_t a2, uint32_t a3,
                                        uint32_t b0, uint32_t b1) {
    asm volatile(
        "mma.sync.aligned.m16n8k16.row.col.f32.f16.f16.f32 "
        "{%0,%1,%2,%3}, {%4,%5,%6,%7}, {%8,%9}, {%0,%1,%2,%3};"
        : "+f"(d[0]), "+f"(d[1]), "+f"(d[2]), "+f"(d[3])
        : "r"(a0), "r"(a1), "r"(a2), "r"(a3), "r"(b0), "r"(b1));
}

#define FMA_X2(acc, a, bb) \
    asm("fma.rn.f32x2 %0, %1, %2, %0;" : "+l"(acc) : "l"(a), "l"(bb))

// ---------------------------------------------------------------------------
// Projection kernel
//   q' = tf32_rna(log2e * (Wq x + bq))        [b][n][m]
//   k' = tf32_rna(Wk x + bk), m-interleaved   [b][n][0,4,1,5,2,6,3,7]
//   v  = fp16(Wv x + bv), transposed          [b][c][n]
// ---------------------------------------------------------------------------
__global__ __launch_bounds__(256) void proj_kernel(
    const float* __restrict__ x,
    const float* __restrict__ wq, const float* __restrict__ bq,
    const float* __restrict__ wk, const float* __restrict__ bk,
    const float* __restrict__ wv, const float* __restrict__ bv)
{
    __shared__ float s_wvT[CH * CH];     // [c][d], d consecutive
    __shared__ float s_wqT[CH * MID];
    __shared__ float s_wkT[CH * MID];
    __shared__ float s_bq[MID], s_bk[MID], s_bv[CH];

    const int tid = threadIdx.x;
    for (int idx = tid; idx < CH * CH; idx += 256) {
        int d = idx >> 6, c = idx & 63;
        s_wvT[c * CH + d] = wv[idx];
    }
    for (int idx = tid; idx < MID * CH; idx += 256) {
        int m = idx >> 6, c = idx & 63;
        s_wqT[c * MID + m] = wq[idx];
        s_wkT[c * MID + m] = wk[idx];
    }
    if (tid < MID) { s_bq[tid] = bq[tid]; s_bk[tid] = bk[tid]; }
    if (tid < CH)  { s_bv[tid] = bv[tid]; }
    __syncthreads();

    const int g = blockIdx.x * 256 + tid;    // b*NPIX + n
    const int b = g >> 12;
    const int n = g & (NPIX - 1);

    float q[MID], k[MID];
    ull  vacc[CH / 2];
    #pragma unroll
    for (int m = 0; m < MID; m++) { q[m] = s_bq[m]; k[m] = s_bk[m]; }
    #pragma unroll
    for (int dd = 0; dd < CH / 2; dd++)
        vacc[dd] = *(const ull*)&s_bv[2 * dd];

    const float* xp = x + (size_t)b * CH * NPIX + n;
    for (int c = 0; c < CH; c++) {
        float xv = xp[(size_t)c * NPIX];
        ull xv2;
        asm("mov.b64 %0, {%1, %1};" : "=l"(xv2) : "r"(__float_as_uint(xv)));
        #pragma unroll
        for (int m = 0; m < MID; m++) {
            q[m] = fmaf(s_wqT[c * MID + m], xv, q[m]);
            k[m] = fmaf(s_wkT[c * MID + m], xv, k[m]);
        }
        #pragma unroll
        for (int dd = 0; dd < CH / 2; dd++) {
            ull w2 = *(const ull*)&s_wvT[c * CH + 2 * dd];
            FMA_X2(vacc[dd], w2, xv2);
        }
    }

    const float LOG2E = 1.4426950408889634f;
    #pragma unroll
    for (int m = 0; m < MID; m++) {
        q[m] = f2tf32r(q[m] * LOG2E);
        k[m] = f2tf32r(k[m]);
    }

    float4* qo = (float4*)&g_q[(size_t)g * MID];
    qo[0] = make_float4(q[0], q[1], q[2], q[3]);
    qo[1] = make_float4(q[4], q[5], q[6], q[7]);
    // K interleaved: pos 2t = m t, pos 2t+1 = m t+4
    float4* ko = (float4*)&g_k[(size_t)g * MID];
    ko[0] = make_float4(k[0], k[4], k[1], k[5]);
    ko[1] = make_float4(k[2], k[6], k[3], k[7]);
    // V transposed fp16 (lane-consecutive n -> coalesced)
    #pragma unroll
    for (int dd = 0; dd < CH / 2; dd++) {
        float2 vp = *(float2*)&vacc[dd];
        g_v[((size_t)(b * CH + 2 * dd)) * NPIX + n]     = __float2half_rn(vp.x);
        g_v[((size_t)(b * CH + 2 * dd + 1)) * NPIX + n] = __float2half_rn(vp.y);
    }
}

// ---------------------------------------------------------------------------
// Attention kernel.
// Block = (b, 128-query tile); warp w owns i-rows [16w, 16w+16).
// Per 64-j tile, per warp (4 chunk-pairs):
//   2x S-MMA tf32 k8 (A = q regs, B = interleaved K row, C init = -16)
//   8x ex2 -> e = 2^(s' - 16)  (shift cancels exactly in num/Z;
//      -16 keeps e < 2^16 in fp16 even for quadratic-form logit tails
//      up to s' ~ 32, while underflow loss stays ~1e-5 relative)
//   4x cvt.rn.f16x2 pack       (S D-frags -> fp16 A-frags, zero shuffles)
//   8x PV-MMA fp16 k16 (B = adjacent-j half2 from V tile, LDS.32)
//   1x Z-MMA fp16 (B = ones)
// k-permutation: A k-slots {2t,2t+1,2t+8,2t+9} <-> j {jbA+2t, jbA+2t+1,
// jbB+2t, jbB+2t+1}; sum over k is permutation-invariant.
// ---------------------------------------------------------------------------
// dyn SMEM (floats):
//   V0 @0 (2304 = 64x72 halves), K0 @2304 (512)
//   V1 @2816,                    K1 @5120 (-> 5632)
//   epilogue: out_s[64][129] @0 (8256), z @8256 (128)
#define VOFF0 0
#define KOFF0 2304
#define VOFF1 2816
#define KOFF1 5120
#define ZOFF  8256
#define SMEM_FLOATS 8384
#define SMEM_BYTES  (SMEM_FLOATS * 4)

__device__ __forceinline__ void prefetch_tile(uint32_t sm, uint32_t vbyte,
                                              int kflt,
                                              const __half* vgh,
                                              const float* kg,
                                              int j0, int tid)
{
    // V tile: 64 c-rows x 64 halves (128B) -> smem stride 144B
    #pragma unroll
    for (int u = 0; u < 2; u++) {
        int ck = u * 256 + tid;           // 0..511
        int c = ck >> 3, j8 = ck & 7;
        cp_async16(sm + vbyte + (uint32_t)(c * 144 + j8 * 16),
                   vgh + (size_t)c * NPIX + j0 + j8 * 8);
    }
    // K tile: 64 x 8 floats = 128 float4
    if (tid < 128) {
        int j = tid >> 1, h = (tid & 1) << 2;
        cp_async16(sm + (uint32_t)(kflt + j * 8 + h) * 4,
                   kg + (size_t)(j0 + j) * MID + h);
    }
}

__global__ __launch_bounds__(256, 2) void attn_kernel(
    const float* __restrict__ x,
    const float* __restrict__ gamma,
    float* __restrict__ out)
{
    extern __shared__ __align__(128) float smem[];
    const uint32_t sm = smem_u32(smem);
    const int tid = threadIdx.x;
    const int wid = tid >> 5;
    const int lid = tid & 31;
    const int g8  = lid >> 2;        // groupID 0..7
    const int tig = lid & 3;         // thread-in-group 0..3
    const int b   = blockIdx.y;
    const int i0g = blockIdx.x * TQ;

    // q A-fragment registers (tf32 S-MMA slots t, t+4 = logical m tig, tig+4)
    const int ia = i0g + wid * 16 + g8;
    const float* qp = g_q + ((size_t)b * NPIX + ia) * MID;
    const uint32_t qA0 = __float_as_uint(qp[tig]);
    const uint32_t qA1 = __float_as_uint(qp[8 * MID + tig]);
    const uint32_t qA2 = __float_as_uint(qp[tig + 4]);
    const uint32_t qA3 = __float_as_uint(qp[8 * MID + tig + 4]);

    float acc[8][4];
    float accz[4];
    #pragma unroll
    for (int ng = 0; ng < 8; ng++)
        #pragma unroll
        for (int r = 0; r < 4; r++) acc[ng][r] = 0.0f;
    #pragma unroll
    for (int r = 0; r < 4; r++) accz[r] = 0.0f;

    const __half* vb = g_v + (size_t)(b * CH) * NPIX;
    const float*  kb = g_k + (size_t)b * NPIX * MID;
    const uint32_t ONEH2 = 0x3C003C00u;   // {1.0h, 1.0h}
    const float NS = -16.0f;              // exponent shift (cancels in num/Z)

    prefetch_tile(sm, VOFF0 * 4, KOFF0, vb, kb, 0, tid);
    CP_COMMIT();

    for (int t = 0; t < NPIX / TJ; t++) {
        CP_WAIT0();
        __syncthreads();
        if (t + 1 < NPIX / TJ) {
            prefetch_tile(sm, (t & 1) ? VOFF0 * 4 : VOFF1 * 4,
                          (t & 1) ? KOFF0 : KOFF1,
                          vb, kb, (t + 1) * TJ, tid);
            CP_COMMIT();
        }
        const __half* vsh = (const __half*)(smem + ((t & 1) ? VOFF1 : VOFF0));
        const float*  ks  = smem + ((t & 1) ? KOFF1 : KOFF0);

        #pragma unroll
        for (int p4 = 0; p4 < 4; p4++) {
            const int jnA = p4 * 2, jnB = jnA + 1;

            // ---- two S-MMAs (C init = -16 -> e = 2^(s'-16)) ----
            float2 kfA = *(const float2*)&ks[(jnA * 8 + g8) * 8 + 2 * tig];
            float sA[4] = {NS, NS, NS, NS};
            mma_tf32(sA, qA0, qA1, qA2, qA3,
                     __float_as_uint(kfA.x), __float_as_uint(kfA.y));
            float2 kfB = *(const float2*)&ks[(jnB * 8 + g8) * 8 + 2 * tig];
            float sB[4] = {NS, NS, NS, NS};
            mma_tf32(sB, qA0, qA1, qA2, qA3,
                     __float_as_uint(kfB.x), __float_as_uint(kfB.y));

            // ---- exp2 + pack to fp16 A-fragments ----
            // D-frag: d0=(g,2t) d1=(g,2t+1) d2=(g+8,2t) d3=(g+8,2t+1)
            // A-frag k16: a0=(g, k 2t,2t+1) a1=(g+8, ...) a2/a3 = chunk B
            uint32_t a0 = packh(ex2(sA[0]), ex2(sA[1]));
            uint32_t a1 = packh(ex2(sA[2]), ex2(sA[3]));
            uint32_t a2 = packh(ex2(sB[0]), ex2(sB[1]));
            uint32_t a3 = packh(ex2(sB[2]), ex2(sB[3]));

            const int jA = jnA * 8 + 2 * tig;
            const int jB = jnB * 8 + 2 * tig;
            #pragma unroll
            for (int ng = 0; ng < 8; ng++) {
                const int c = ng * 8 + g8;
                uint32_t b0 = *(const uint32_t*)(vsh + c * VSTR + jA);
                uint32_t b1 = *(const uint32_t*)(vsh + c * VSTR + jB);
                mma_f16(acc[ng], a0, a1, a2, a3, b0, b1);
            }
            mma_f16(accz, a0, a1, a2, a3, ONEH2, ONEH2);
        }
        __syncthreads();
    }

    // ---- epilogue: stage fragments, normalize, coalesced writes ----
    float* out_s = smem;          // [64][129]
    float* z_s   = smem + ZOFF;   // [128]

    #pragma unroll
    for (int ng = 0; ng < 8; ng++) {
        int c = ng * 8 + 2 * tig;
        int i = wid * 16 + g8;
        out_s[c * 129 + i]           = acc[ng][0];
        out_s[(c + 1) * 129 + i]     = acc[ng][1];
        out_s[c * 129 + i + 8]       = acc[ng][2];
        out_s[(c + 1) * 129 + i + 8] = acc[ng][3];
    }
    z_s[wid * 16 + g8]     = accz[0];
    z_s[wid * 16 + g8 + 8] = accz[2];
    __syncthreads();
    if (tid < 128) z_s[tid] = 1.0f / z_s[tid];
    __syncthreads();

    const float gm = gamma[0];
    #pragma unroll
    for (int r = 0; r < 32; r++) {
        int e  = r * 256 + tid;
        int c  = e >> 7;
        int ii = e & 127;
        size_t gi = ((size_t)(b * CH + c)) * NPIX + i0g + ii;
        out[gi] = fmaf(gm * out_s[c * 129 + ii], z_s[ii], x[gi]);
    }
}

// ---------------------------------------------------------------------------
extern "C" void kernel_launch(void* const* d_in, const int* in_sizes, int n_in,
                              void* d_out, int out_size)
{
    const float* x     = (const float*)d_in[0];
    const float* wq    = (const float*)d_in[1];
    const float* bq    = (const float*)d_in[2];
    const float* wk    = (const float*)d_in[3];
    const float* bk    = (const float*)d_in[4];
    const float* wv    = (const float*)d_in[5];
    const float* bv    = (const float*)d_in[6];
    const float* gamma = (const float*)d_in[7];
    float* out = (float*)d_out;

    cudaFuncSetAttribute(attn_kernel,
                         cudaFuncAttributeMaxDynamicSharedMemorySize,
                         SMEM_BYTES);

    proj_kernel<<<(BATCH * NPIX) / 256, 256>>>(x, wq, bq, wk, bk, wv, bv);
    attn_kernel<<<dim3(NPIX / TQ, BATCH), 256, SMEM_BYTES>>>(x, gamma, out);
}

// round 16
// speedup vs baseline: 8.5681x; 1.0440x over previous
#include <cuda_runtime.h>
#include <cuda_fp16.h>
#include <cstdint>

typedef unsigned long long ull;

#define BATCH 8
#define CH    64
#define MID   8
#define NPIX  4096
#define TQ    128
#define TJ    128
#define VSTR  72            // V smem row stride in halves (64 c + 8 pad) = 144B

// Scratch (no allocations allowed -> __device__ globals)
__device__ __half g_q[BATCH * NPIX * MID];  // [b][i][m'] slots (m0,m4,m1,m5,m2,m6,m3,m7), pre-scaled log2e
__device__ __half g_k[BATCH * NPIX * MID];  // [b][j][m'] same interleave
__device__ __half g_v[BATCH * NPIX * CH];   // [b][n][c]  j-major fp16

// ---------------------------------------------------------------------------
// helpers
// ---------------------------------------------------------------------------
__device__ __forceinline__ uint32_t smem_u32(const void* p) {
    uint32_t a;
    asm("{ .reg .u64 t; cvta.to.shared.u64 t, %1; cvt.u32.u64 %0, t; }"
        : "=r"(a) : "l"(p));
    return a;
}
__device__ __forceinline__ void cp_async16(uint32_t dst, const void* src) {
    asm volatile("cp.async.cg.shared.global [%0], [%1], 16;"
                 :: "r"(dst), "l"(src) : "memory");
}
#define CP_COMMIT()  asm volatile("cp.async.commit_group;" ::: "memory")
#define CP_WAIT0()   asm volatile("cp.async.wait_group 0;" ::: "memory")

__device__ __forceinline__ float ex2(float f) {
    float r;
    asm("ex2.approx.f32 %0, %1;" : "=f"(r) : "f"(f));
    return r;
}
// pack two f32 -> f16x2 (lo = first arg in low half)
__device__ __forceinline__ uint32_t packh(float lo, float hi) {
    uint32_t d;
    asm("cvt.rn.f16x2.f32 %0, %1, %2;" : "=r"(d) : "f"(hi), "f"(lo));
    return d;
}

// m16n8k8 fp16 MMA, f32 accum (for S)
__device__ __forceinline__ void mma_f16k8(float* d, uint32_t a0, uint32_t a1,
                                          uint32_t b0) {
    asm volatile(
        "mma.sync.aligned.m16n8k8.row.col.f32.f16.f16.f32 "
        "{%0,%1,%2,%3}, {%4,%5}, {%6}, {%0,%1,%2,%3};"
        : "+f"(d[0]), "+f"(d[1]), "+f"(d[2]), "+f"(d[3])
        : "r"(a0), "r"(a1), "r"(b0));
}
// m16n8k16 fp16 MMA, f32 accum (for PV / Z)
__device__ __forceinline__ void mma_f16(float* d,
                                        uint32_t a0, uint32_t a1,
                                        uint32_t a2, uint32_t a3,
                                        uint32_t b0, uint32_t b1) {
    asm volatile(
        "mma.sync.aligned.m16n8k16.row.col.f32.f16.f16.f32 "
        "{%0,%1,%2,%3}, {%4,%5,%6,%7}, {%8,%9}, {%0,%1,%2,%3};"
        : "+f"(d[0]), "+f"(d[1]), "+f"(d[2]), "+f"(d[3])
        : "r"(a0), "r"(a1), "r"(a2), "r"(a3), "r"(b0), "r"(b1));
}
// ldmatrix x4 transposed (B-operand loader)
__device__ __forceinline__ void ldsm_x4t(uint32_t& r0, uint32_t& r1,
                                         uint32_t& r2, uint32_t& r3,
                                         uint32_t addr) {
    asm volatile(
        "ldmatrix.sync.aligned.m8n8.x4.trans.shared.b16 {%0,%1,%2,%3}, [%4];"
        : "=r"(r0), "=r"(r1), "=r"(r2), "=r"(r3) : "r"(addr));
}

#define FMA_X2(acc, a, bb) \
    asm("fma.rn.f32x2 %0, %1, %2, %0;" : "+l"(acc) : "l"(a), "l"(bb))

// ---------------------------------------------------------------------------
// Projection kernel
//   q' = fp16(log2e * (Wq x + bq)), m-interleaved  [b][n][8]
//   k' = fp16(Wk x + bk), m-interleaved            [b][n][8]
//   v  = fp16(Wv x + bv), j-major                  [b][n][64]
// ---------------------------------------------------------------------------
__global__ __launch_bounds__(256) void proj_kernel(
    const float* __restrict__ x,
    const float* __restrict__ wq, const float* __restrict__ bq,
    const float* __restrict__ wk, const float* __restrict__ bk,
    const float* __restrict__ wv, const float* __restrict__ bv)
{
    __shared__ float s_wvT[CH * CH];     // [c][d], d consecutive
    __shared__ float s_wqT[CH * MID];
    __shared__ float s_wkT[CH * MID];
    __shared__ float s_bq[MID], s_bk[MID], s_bv[CH];

    const int tid = threadIdx.x;
    for (int idx = tid; idx < CH * CH; idx += 256) {
        int d = idx >> 6, c = idx & 63;
        s_wvT[c * CH + d] = wv[idx];
    }
    for (int idx = tid; idx < MID * CH; idx += 256) {
        int m = idx >> 6, c = idx & 63;
        s_wqT[c * MID + m] = wq[idx];
        s_wkT[c * MID + m] = wk[idx];
    }
    if (tid < MID) { s_bq[tid] = bq[tid]; s_bk[tid] = bk[tid]; }
    if (tid < CH)  { s_bv[tid] = bv[tid]; }
    __syncthreads();

    const int g = blockIdx.x * 256 + tid;    // b*NPIX + n
    const int b = g >> 12;
    const int n = g & (NPIX - 1);

    float q[MID], k[MID];
    ull  vacc[CH / 2];
    #pragma unroll
    for (int m = 0; m < MID; m++) { q[m] = s_bq[m]; k[m] = s_bk[m]; }
    #pragma unroll
    for (int dd = 0; dd < CH / 2; dd++)
        vacc[dd] = *(const ull*)&s_bv[2 * dd];

    const float* xp = x + (size_t)b * CH * NPIX + n;
    for (int c = 0; c < CH; c++) {
        float xv = xp[(size_t)c * NPIX];
        ull xv2;
        asm("mov.b64 %0, {%1, %1};" : "=l"(xv2) : "r"(__float_as_uint(xv)));
        #pragma unroll
        for (int m = 0; m < MID; m++) {
            q[m] = fmaf(s_wqT[c * MID + m], xv, q[m]);
            k[m] = fmaf(s_wkT[c * MID + m], xv, k[m]);
        }
        #pragma unroll
        for (int dd = 0; dd < CH / 2; dd++) {
            ull w2 = *(const ull*)&s_wvT[c * CH + 2 * dd];
            FMA_X2(vacc[dd], w2, xv2);
        }
    }

    const float LOG2E = 1.4426950408889634f;
    // q/k fp16, interleave slots (2t, 2t+1) = (m t, m t+4)
    uint4 qo, ko;
    qo.x = packh(q[0] * LOG2E, q[4] * LOG2E);
    qo.y = packh(q[1] * LOG2E, q[5] * LOG2E);
    qo.z = packh(q[2] * LOG2E, q[6] * LOG2E);
    qo.w = packh(q[3] * LOG2E, q[7] * LOG2E);
    ko.x = packh(k[0], k[4]);
    ko.y = packh(k[1], k[5]);
    ko.z = packh(k[2], k[6]);
    ko.w = packh(k[3], k[7]);
    *(uint4*)&g_q[(size_t)g * MID] = qo;
    *(uint4*)&g_k[(size_t)g * MID] = ko;

    // v fp16 j-major: 64 halves contiguous per pixel
    uint4* vo = (uint4*)&g_v[(size_t)g * CH];
    #pragma unroll
    for (int r = 0; r < 4; r++) {
        uint4 w;
        float2 p0 = *(float2*)&vacc[r * 8 + 0];
        float2 p1 = *(float2*)&vacc[r * 8 + 1];
        float2 p2 = *(float2*)&vacc[r * 8 + 2];
        float2 p3 = *(float2*)&vacc[r * 8 + 3];
        w.x = packh(p0.x, p0.y); w.y = packh(p1.x, p1.y);
        w.z = packh(p2.x, p2.y); w.w = packh(p3.x, p3.y);
        vo[r * 2] = w;
        float2 p4 = *(float2*)&vacc[r * 8 + 4];
        float2 p5 = *(float2*)&vacc[r * 8 + 5];
        float2 p6 = *(float2*)&vacc[r * 8 + 6];
        float2 p7 = *(float2*)&vacc[r * 8 + 7];
        w.x = packh(p4.x, p4.y); w.y = packh(p5.x, p5.y);
        w.z = packh(p6.x, p6.y); w.w = packh(p7.x, p7.y);
        vo[r * 2 + 1] = w;
    }
}

// ---------------------------------------------------------------------------
// Attention kernel.
// Block = (b, 128-query tile); warp w owns i-rows [16w, 16w+16).
// Per 128-j tile, per warp (8 chunks of 16 j):
//   2x S-MMA fp16 k8 (A = q regs, B = interleaved K row LDS.32, C init = -16)
//   8x ex2 -> e = 2^(s'-16) (shift cancels exactly in num/Z)
//   4x cvt.rn.f16x2 pack    (S D-frags -> fp16 A-frags, identity k->j map)
//   4x ldmatrix.x4.trans    (V j-major tile -> B-frags for 8 PV MMAs)
//   8x PV-MMA fp16 k16 + 1x Z-MMA (B = ones)
// ---------------------------------------------------------------------------
// byte offsets in dyn smem:
#define VB0 0u          // 128 * 144 = 18432
#define KB0 18432u      // 128 * 16  = 2048
#define VB1 20480u
#define KB1 38912u
#define SMEM_BYTES 40960
// epilogue staging (reuses ring): out_s[64][129] f32 @0, z @ float 8256
#define ZOFF 8256

__device__ __forceinline__ void prefetch_tile(uint32_t sm, uint32_t vbyte,
                                              uint32_t kbyte,
                                              const __half* vg,
                                              const __half* kg,
                                              int j0, int tid)
{
    // V tile: 128 j-rows x 64 halves (128B each) -> smem stride 144B
    #pragma unroll
    for (int u = 0; u < 4; u++) {
        int idx = u * 256 + tid;          // 0..1023
        int j = idx >> 3, ch = idx & 7;
        cp_async16(sm + vbyte + (uint32_t)(j * 144 + ch * 16),
                   vg + (size_t)(j0 + j) * CH + ch * 8);
    }
    // K tile: 128 j-rows x 8 halves (16B each)
    if (tid < 128)
        cp_async16(sm + kbyte + (uint32_t)tid * 16,
                   kg + (size_t)(j0 + tid) * MID);
}

__global__ __launch_bounds__(256, 2) void attn_kernel(
    const float* __restrict__ x,
    const float* __restrict__ gamma,
    float* __restrict__ out)
{
    extern __shared__ __align__(128) float smem[];
    const uint32_t sm = smem_u32(smem);
    const char* smc = (const char*)smem;
    const int tid = threadIdx.x;
    const int wid = tid >> 5;
    const int lid = tid & 31;
    const int g8  = lid >> 2;        // groupID 0..7
    const int tig = lid & 3;         // thread-in-group 0..3
    const int b   = blockIdx.y;
    const int i0g = blockIdx.x * TQ;

    // q A-fragment (fp16 k8): a0 = row g slots (2t,2t+1); a1 = row g+8
    const int ia = i0g + wid * 16 + g8;
    const __half* qh = g_q + ((size_t)b * NPIX + ia) * MID;
    const uint32_t qa0 = *(const uint32_t*)(qh + 2 * tig);
    const uint32_t qa1 = *(const uint32_t*)(qh + 8 * MID + 2 * tig);

    // per-thread ldmatrix base: sel = lid>>3, row r = lid&7
    //   joff = (sel&1)*8 + r  (matrix pair rows),  coff = (sel>>1)*8
    const int sel  = lid >> 3;
    const int joff = ((sel & 1) << 3) + (lid & 7);
    const int coff = (sel >> 1) << 3;
    const uint32_t lm_off = (uint32_t)(joff * 144 + coff * 2);

    float acc[8][4];
    float accz[4];
    #pragma unroll
    for (int ng = 0; ng < 8; ng++)
        #pragma unroll
        for (int r = 0; r < 4; r++) acc[ng][r] = 0.0f;
    #pragma unroll
    for (int r = 0; r < 4; r++) accz[r] = 0.0f;

    const __half* vb = g_v + (size_t)b * NPIX * CH;
    const __half* kb = g_k + (size_t)b * NPIX * MID;
    const uint32_t ONEH2 = 0x3C003C00u;   // {1.0h, 1.0h}
    const float NS = -16.0f;              // exponent shift (cancels in num/Z)

    prefetch_tile(sm, VB0, KB0, vb, kb, 0, tid);
    CP_COMMIT();

    for (int t = 0; t < NPIX / TJ; t++) {
        CP_WAIT0();
        __syncthreads();
        if (t + 1 < NPIX / TJ) {
            prefetch_tile(sm, (t & 1) ? VB0 : VB1, (t & 1) ? KB0 : KB1,
                          vb, kb, (t + 1) * TJ, tid);
            CP_COMMIT();
        }
        const uint32_t vbuf = sm + ((t & 1) ? VB1 : VB0);
        const uint32_t kofs = (t & 1) ? KB1 : KB0;
        const char* kc = smc + kofs + g8 * 16 + tig * 4;

        #pragma unroll
        for (int p4 = 0; p4 < 8; p4++) {
            // ---- two S-MMAs over 16 j (C init = -16 -> e = 2^(s'-16)) ----
            uint32_t kf0 = *(const uint32_t*)(kc + p4 * 256);
            uint32_t kf1 = *(const uint32_t*)(kc + p4 * 256 + 128);
            float sA[4] = {NS, NS, NS, NS};
            float sB[4] = {NS, NS, NS, NS};
            mma_f16k8(sA, qa0, qa1, kf0);
            mma_f16k8(sB, qa0, qa1, kf1);

            // ---- exp2 + pack to fp16 A-frags (identity k->j) ----
            uint32_t a0 = packh(ex2(sA[0]), ex2(sA[1]));
            uint32_t a1 = packh(ex2(sA[2]), ex2(sA[3]));
            uint32_t a2 = packh(ex2(sB[0]), ex2(sB[1]));
            uint32_t a3 = packh(ex2(sB[2]), ex2(sB[3]));

            // ---- V B-frags via ldmatrix, 8 PV MMAs + Z ----
            const uint32_t lmbase = vbuf + lm_off + (uint32_t)(p4 * 2304);
            #pragma unroll
            for (int np = 0; np < 4; np++) {
                uint32_t r0, r1, r2, r3;
                ldsm_x4t(r0, r1, r2, r3, lmbase + np * 32);
                mma_f16(acc[np * 2],     a0, a1, a2, a3, r0, r1);
                mma_f16(acc[np * 2 + 1], a0, a1, a2, a3, r2, r3);
            }
            mma_f16(accz, a0, a1, a2, a3, ONEH2, ONEH2);
        }
        __syncthreads();
    }

    // ---- epilogue: stage fragments, normalize, coalesced writes ----
    float* out_s = smem;          // [64][129]
    float* z_s   = smem + ZOFF;   // [128]

    #pragma unroll
    for (int ng = 0; ng < 8; ng++) {
        int c = ng * 8 + 2 * tig;
        int i = wid * 16 + g8;
        out_s[c * 129 + i]           = acc[ng][0];
        out_s[(c + 1) * 129 + i]     = acc[ng][1];
        out_s[c * 129 + i + 8]       = acc[ng][2];
        out_s[(c + 1) * 129 + i + 8] = acc[ng][3];
    }
    z_s[wid * 16 + g8]     = accz[0];
    z_s[wid * 16 + g8 + 8] = accz[2];
    __syncthreads();
    if (tid < 128) z_s[tid] = 1.0f / z_s[tid];
    __syncthreads();

    const float gm = gamma[0];
    #pragma unroll
    for (int r = 0; r < 32; r++) {
        int e  = r * 256 + tid;
        int c  = e >> 7;
        int ii = e & 127;
        size_t gi = ((size_t)(b * CH + c)) * NPIX + i0g + ii;
        out[gi] = fmaf(gm * out_s[c * 129 + ii], z_s[ii], x[gi]);
    }
}

// ---------------------------------------------------------------------------
extern "C" void kernel_launch(void* const* d_in, const int* in_sizes, int n_in,
                              void* d_out, int out_size)
{
    const float* x     = (const float*)d_in[0];
    const float* wq    = (const float*)d_in[1];
    const float* bq    = (const float*)d_in[2];
    const float* wk    = (const float*)d_in[3];
    const float* bk    = (const float*)d_in[4];
    const float* wv    = (const float*)d_in[5];
    const float* bv    = (const float*)d_in[6];
    const float* gamma = (const float*)d_in[7];
    float* out = (float*)d_out;

    cudaFuncSetAttribute(attn_kernel,
                         cudaFuncAttributeMaxDynamicSharedMemorySize,
                         SMEM_BYTES);

    proj_kernel<<<(BATCH * NPIX) / 256, 256>>>(x, wq, bq, wk, bk, wv, bv);
    attn_kernel<<<dim3(NPIX / TQ, BATCH), 256, SMEM_BYTES>>>(x, gamma, out);
}